// round 1
// baseline (speedup 1.0000x reference)
#include <cuda_runtime.h>
#include <cuda_bf16.h>
#include <math.h>

// Problem constants
constexpr int Bc  = 4;
constexpr int Sq  = 2048;
constexpr int Dm  = 1024;
constexpr int Hh  = 16;
constexpr int HDd = 64;
constexpr int Mtot = Bc * Sq;           // 8192

// Scratch (device globals: allocation-free per harness rules)
__device__ float g_q[(size_t)Mtot * Dm];
__device__ float g_k[(size_t)Mtot * Dm];
__device__ float g_v[(size_t)Mtot * Dm];
__device__ float g_ctx[(size_t)Mtot * Dm];

// ---------------------------------------------------------------------------
// SGEMM: out = A[M,K] @ W[N,K]^T + bias, M=8192, N=K=1024.
// SPLIT_HEADS=true writes out in [B,H,S,HD] layout; else plain [M,N].
// 128x128 block tile, BK=16, 8x8 per thread, 256 threads.
// ---------------------------------------------------------------------------
template <bool SPLIT_HEADS>
__global__ __launch_bounds__(256)
void gemm_bias_kernel(const float* __restrict__ A,
                      const float* __restrict__ W,
                      const float* __restrict__ bias,
                      float* __restrict__ out)
{
    constexpr int K = Dm;
    __shared__ float As[16][128];
    __shared__ float Bs[16][128];

    const int t  = threadIdx.x;
    const int m0 = blockIdx.y * 128;
    const int n0 = blockIdx.x * 128;
    const int tx = t & 15;    // col group
    const int ty = t >> 4;    // row group

    float acc[8][8];
#pragma unroll
    for (int i = 0; i < 8; i++)
#pragma unroll
        for (int j = 0; j < 8; j++) acc[i][j] = 0.0f;

    const int lrow = t >> 2;          // 0..63
    const int lcol = (t & 3) * 4;     // 0,4,8,12

    for (int kt = 0; kt < K; kt += 16) {
#pragma unroll
        for (int r = 0; r < 2; r++) {
            const int row = lrow + r * 64;
            float4 av = *(const float4*)(A + (size_t)(m0 + row) * K + kt + lcol);
            As[lcol + 0][row] = av.x;
            As[lcol + 1][row] = av.y;
            As[lcol + 2][row] = av.z;
            As[lcol + 3][row] = av.w;
            float4 wv = *(const float4*)(W + (size_t)(n0 + row) * K + kt + lcol);
            Bs[lcol + 0][row] = wv.x;
            Bs[lcol + 1][row] = wv.y;
            Bs[lcol + 2][row] = wv.z;
            Bs[lcol + 3][row] = wv.w;
        }
        __syncthreads();

#pragma unroll
        for (int k = 0; k < 16; k++) {
            float a[8], b[8];
            *(float4*)&a[0] = *(const float4*)&As[k][ty * 8];
            *(float4*)&a[4] = *(const float4*)&As[k][ty * 8 + 4];
            *(float4*)&b[0] = *(const float4*)&Bs[k][tx * 8];
            *(float4*)&b[4] = *(const float4*)&Bs[k][tx * 8 + 4];
#pragma unroll
            for (int i = 0; i < 8; i++)
#pragma unroll
                for (int j = 0; j < 8; j++)
                    acc[i][j] = fmaf(a[i], b[j], acc[i][j]);
        }
        __syncthreads();
    }

#pragma unroll
    for (int i = 0; i < 8; i++) {
        const int m  = m0 + ty * 8 + i;
        const int b_ = m / Sq;
        const int s_ = m % Sq;
#pragma unroll
        for (int j = 0; j < 8; j++) {
            const int n = n0 + tx * 8 + j;
            const float val = acc[i][j] + bias[n];
            if (SPLIT_HEADS) {
                const int h_ = n >> 6;
                const int d_ = n & 63;
                out[(((size_t)(b_ * Hh + h_)) * Sq + s_) * HDd + d_] = val;
            } else {
                out[(size_t)m * Dm + n] = val;
            }
        }
    }
}

// ---------------------------------------------------------------------------
// Flash attention: one block = (qtile of 64 queries, head h, batch b).
// 256 threads; each thread owns a 4x4 tile of the 64x64 score block
// (rows r0..r0+3, cols c0..c0+3) and 4x4 of the 64-wide output.
// Online softmax with causal + pad masking. fp32 throughout.
// ---------------------------------------------------------------------------
constexpr int QS_STRIDE = 68;   // padded row stride (floats) for Qs/Kt/Ps
constexpr int SMEM_FLOATS = 64 * QS_STRIDE * 3 + 64 * 64;   // Qs,Kt,Ps + Vs
constexpr int SMEM_BYTES  = SMEM_FLOATS * 4 + 64 * 4;       // + mask ints

__global__ __launch_bounds__(256)
void flash_attn_kernel(const float* __restrict__ Qg,
                       const float* __restrict__ Kg,
                       const float* __restrict__ Vg,
                       const int*   __restrict__ maskg,
                       float* __restrict__ ctx)
{
    extern __shared__ float sm[];
    float* Qs = sm;                         // [64][68]
    float* Kt = Qs + 64 * QS_STRIDE;        // [64][68]  (Kt[d][c])
    float* Vs = Kt + 64 * QS_STRIDE;        // [64][64]
    float* Ps = Vs + 64 * 64;               // [64][68]
    int*   msk = (int*)(Ps + 64 * QS_STRIDE);

    const int t  = threadIdx.x;
    const int qt = blockIdx.x;
    const int h  = blockIdx.y;
    const int b  = blockIdx.z;
    const int tc = t & 15;
    const int tr = t >> 4;
    const int r0 = tr * 4;
    const int c0 = tc * 4;

    const size_t head_base = ((size_t)(b * Hh + h)) * Sq * HDd;
    const float* Qp = Qg + head_base + (size_t)qt * 64 * HDd;

    // Load Q tile, folding in the softmax scale (HD^-0.5 = 0.125)
    for (int idx = t; idx < 64 * 16; idx += 256) {
        const int row = idx >> 4;
        const int c4  = (idx & 15) << 2;
        float4 qv = *(const float4*)(Qp + row * HDd + c4);
        qv.x *= 0.125f; qv.y *= 0.125f; qv.z *= 0.125f; qv.w *= 0.125f;
        *(float4*)&Qs[row * QS_STRIDE + c4] = qv;
    }

    float m_i[4], l_i[4], o[4][4];
#pragma unroll
    for (int i = 0; i < 4; i++) {
        m_i[i] = -INFINITY;
        l_i[i] = 0.0f;
#pragma unroll
        for (int j = 0; j < 4; j++) o[i][j] = 0.0f;
    }

    for (int kt2 = 0; kt2 <= qt; kt2++) {
        const float* Kp = Kg + head_base + (size_t)kt2 * 64 * HDd;
        const float* Vp = Vg + head_base + (size_t)kt2 * 64 * HDd;

        __syncthreads();   // previous-iter readers of Kt/Vs/Ps are done
        for (int idx = t; idx < 64 * 16; idx += 256) {
            const int row = idx >> 4;
            const int c4  = (idx & 15) << 2;
            const float4 kv = *(const float4*)(Kp + row * HDd + c4);
            Kt[(c4 + 0) * QS_STRIDE + row] = kv.x;
            Kt[(c4 + 1) * QS_STRIDE + row] = kv.y;
            Kt[(c4 + 2) * QS_STRIDE + row] = kv.z;
            Kt[(c4 + 3) * QS_STRIDE + row] = kv.w;
            const float4 vv = *(const float4*)(Vp + row * HDd + c4);
            *(float4*)&Vs[row * 64 + c4] = vv;
        }
        if (t < 64) msk[t] = maskg[b * Sq + kt2 * 64 + t];
        __syncthreads();

        // S = Q @ K^T  (thread: 4x4)
        float s4[4][4];
#pragma unroll
        for (int i = 0; i < 4; i++)
#pragma unroll
            for (int j = 0; j < 4; j++) s4[i][j] = 0.0f;

#pragma unroll 4
        for (int d4 = 0; d4 < 64; d4 += 4) {
            const float4 k0 = *(const float4*)&Kt[(d4 + 0) * QS_STRIDE + c0];
            const float4 k1 = *(const float4*)&Kt[(d4 + 1) * QS_STRIDE + c0];
            const float4 k2 = *(const float4*)&Kt[(d4 + 2) * QS_STRIDE + c0];
            const float4 k3 = *(const float4*)&Kt[(d4 + 3) * QS_STRIDE + c0];
#pragma unroll
            for (int i = 0; i < 4; i++) {
                const float4 qv = *(const float4*)&Qs[(r0 + i) * QS_STRIDE + d4];
                s4[i][0] += qv.x * k0.x + qv.y * k1.x + qv.z * k2.x + qv.w * k3.x;
                s4[i][1] += qv.x * k0.y + qv.y * k1.y + qv.z * k2.y + qv.w * k3.y;
                s4[i][2] += qv.x * k0.z + qv.y * k1.z + qv.z * k2.z + qv.w * k3.z;
                s4[i][3] += qv.x * k0.w + qv.y * k1.w + qv.z * k2.w + qv.w * k3.w;
            }
        }

        // Masking: pad overrides causal (reference order)
        const bool diag = (kt2 == qt);
#pragma unroll
        for (int i = 0; i < 4; i++) {
#pragma unroll
            for (int j = 0; j < 4; j++) {
                const int kj = c0 + j;
                if (msk[kj] == 0)               s4[i][j] = -1e9f;
                else if (diag && kj > (r0 + i)) s4[i][j] = -INFINITY;
            }
        }

        // Online softmax (row stats over 16 lanes of the half-warp group)
#pragma unroll
        for (int i = 0; i < 4; i++) {
            float mloc = fmaxf(fmaxf(s4[i][0], s4[i][1]), fmaxf(s4[i][2], s4[i][3]));
#pragma unroll
            for (int off = 1; off < 16; off <<= 1)
                mloc = fmaxf(mloc, __shfl_xor_sync(0xffffffffu, mloc, off));
            const float mnew  = fmaxf(m_i[i], mloc);
            const float alpha = __expf(m_i[i] - mnew);
            const float p0 = __expf(s4[i][0] - mnew);
            const float p1 = __expf(s4[i][1] - mnew);
            const float p2 = __expf(s4[i][2] - mnew);
            const float p3 = __expf(s4[i][3] - mnew);
            float ls = p0 + p1 + p2 + p3;
#pragma unroll
            for (int off = 1; off < 16; off <<= 1)
                ls += __shfl_xor_sync(0xffffffffu, ls, off);
            l_i[i] = l_i[i] * alpha + ls;
            m_i[i] = mnew;
            o[i][0] *= alpha; o[i][1] *= alpha; o[i][2] *= alpha; o[i][3] *= alpha;
            float4 pv; pv.x = p0; pv.y = p1; pv.z = p2; pv.w = p3;
            *(float4*)&Ps[(r0 + i) * QS_STRIDE + c0] = pv;
        }
        __syncthreads();

        // O += P @ V  (thread: rows r0..+3, output cols c0..+3)
#pragma unroll 4
        for (int c4 = 0; c4 < 64; c4 += 4) {
            const float4 v0 = *(const float4*)&Vs[(c4 + 0) * 64 + c0];
            const float4 v1 = *(const float4*)&Vs[(c4 + 1) * 64 + c0];
            const float4 v2 = *(const float4*)&Vs[(c4 + 2) * 64 + c0];
            const float4 v3 = *(const float4*)&Vs[(c4 + 3) * 64 + c0];
#pragma unroll
            for (int i = 0; i < 4; i++) {
                const float4 pv = *(const float4*)&Ps[(r0 + i) * QS_STRIDE + c4];
                o[i][0] += pv.x * v0.x + pv.y * v1.x + pv.z * v2.x + pv.w * v3.x;
                o[i][1] += pv.x * v0.y + pv.y * v1.y + pv.z * v2.y + pv.w * v3.y;
                o[i][2] += pv.x * v0.z + pv.y * v1.z + pv.z * v2.z + pv.w * v3.z;
                o[i][3] += pv.x * v0.w + pv.y * v1.w + pv.z * v2.w + pv.w * v3.w;
            }
        }
    }

    // Normalize + write ctx in [B,S,D] layout
#pragma unroll
    for (int i = 0; i < 4; i++) {
        const float inv = 1.0f / l_i[i];
        float4 ov;
        ov.x = o[i][0] * inv; ov.y = o[i][1] * inv;
        ov.z = o[i][2] * inv; ov.w = o[i][3] * inv;
        const size_t row = (size_t)b * Sq + qt * 64 + r0 + i;
        *(float4*)(ctx + row * Dm + h * HDd + c0) = ov;
    }
}

// ---------------------------------------------------------------------------
// Launch
// ---------------------------------------------------------------------------
extern "C" void kernel_launch(void* const* d_in, const int* in_sizes, int n_in,
                              void* d_out, int out_size)
{
    // Identify inputs by element count (robust to metadata ordering):
    // x: 8388608 f32, mask: 8192 i32, W*: 1048576 f32 (order q,k,v,o), b*: 1024 f32.
    const float* x  = nullptr;
    const int*   am = nullptr;
    const float* Ws[4] = {nullptr, nullptr, nullptr, nullptr};
    const float* bs[4] = {nullptr, nullptr, nullptr, nullptr};
    int wi = 0, bi = 0;
    for (int i = 0; i < n_in; i++) {
        const long sz = in_sizes[i];
        if (sz == (long)Mtot * Dm)      x = (const float*)d_in[i];
        else if (sz == (long)Mtot)      am = (const int*)d_in[i];
        else if (sz == (long)Dm * Dm) { if (wi < 4) Ws[wi++] = (const float*)d_in[i]; }
        else if (sz == (long)Dm)      { if (bi < 4) bs[bi++] = (const float*)d_in[i]; }
    }

    float *qp, *kp, *vp, *cp;
    cudaGetSymbolAddress((void**)&qp, g_q);
    cudaGetSymbolAddress((void**)&kp, g_k);
    cudaGetSymbolAddress((void**)&vp, g_v);
    cudaGetSymbolAddress((void**)&cp, g_ctx);

    cudaFuncSetAttribute(flash_attn_kernel,
                         cudaFuncAttributeMaxDynamicSharedMemorySize, SMEM_BYTES);

    const dim3 gg(Dm / 128, Mtot / 128);
    gemm_bias_kernel<true><<<gg, 256>>>(x, Ws[0], bs[0], qp);
    gemm_bias_kernel<true><<<gg, 256>>>(x, Ws[1], bs[1], kp);
    gemm_bias_kernel<true><<<gg, 256>>>(x, Ws[2], bs[2], vp);

    const dim3 ga(Sq / 64, Hh, Bc);
    flash_attn_kernel<<<ga, 256, SMEM_BYTES>>>(qp, kp, vp, am, cp);

    gemm_bias_kernel<false><<<gg, 256>>>(cp, Ws[3], bs[3], (float*)d_out);
}

// round 3
// speedup vs baseline: 1.6087x; 1.6087x over previous
#include <cuda_runtime.h>
#include <cuda_bf16.h>
#include <math.h>
#include <stdint.h>

// Problem constants
constexpr int Bc  = 4;
constexpr int Sq  = 2048;
constexpr int Dm  = 1024;
constexpr int Hh  = 16;
constexpr int HDd = 64;
constexpr int Mtot = Bc * Sq;           // 8192

// Scratch (device globals: allocation-free per harness rules)
__device__ float g_q[(size_t)Mtot * Dm];
__device__ float g_k[(size_t)Mtot * Dm];
__device__ float g_v[(size_t)Mtot * Dm];
__device__ float g_ctx[(size_t)Mtot * Dm];
__device__ __nv_bfloat16 g_xh[(size_t)Mtot * Dm];
__device__ __nv_bfloat16 g_xl[(size_t)Mtot * Dm];
__device__ __nv_bfloat16 g_ch[(size_t)Mtot * Dm];
__device__ __nv_bfloat16 g_cl[(size_t)Mtot * Dm];
__device__ __nv_bfloat16 g_wh[(size_t)4 * Dm * Dm];
__device__ __nv_bfloat16 g_wl[(size_t)4 * Dm * Dm];

// ---------------------------------------------------------------------------
// PTX helpers (sm_80-compatible subset only: ldmatrix / mma.sync / cp.async)
// ---------------------------------------------------------------------------
__device__ __forceinline__ uint32_t smem_u32(const void* p) {
    uint32_t a;
    asm("{ .reg .u64 t; cvta.to.shared.u64 t, %1; cvt.u32.u64 %0, t; }" : "=r"(a) : "l"(p));
    return a;
}
__device__ __forceinline__ void ldm_x4(uint32_t (&r)[4], uint32_t saddr) {
    asm volatile("ldmatrix.sync.aligned.m8n8.x4.shared.b16 {%0,%1,%2,%3}, [%4];"
        : "=r"(r[0]), "=r"(r[1]), "=r"(r[2]), "=r"(r[3]) : "r"(saddr));
}
__device__ __forceinline__ void mma16816(float (&c)[4], const uint32_t (&a)[4],
                                         uint32_t b0, uint32_t b1) {
    asm volatile("mma.sync.aligned.m16n8k16.row.col.f32.bf16.bf16.f32 "
        "{%0,%1,%2,%3}, {%4,%5,%6,%7}, {%8,%9}, {%0,%1,%2,%3};"
        : "+f"(c[0]), "+f"(c[1]), "+f"(c[2]), "+f"(c[3])
        : "r"(a[0]), "r"(a[1]), "r"(a[2]), "r"(a[3]), "r"(b0), "r"(b1));
}
__device__ __forceinline__ void cp16(uint32_t dst, const void* src) {
    asm volatile("cp.async.cg.shared.global [%0], [%1], 16;" :: "r"(dst), "l"(src) : "memory");
}
#define CP_COMMIT() asm volatile("cp.async.commit_group;" ::: "memory")
#define CP_WAIT(n)  asm volatile("cp.async.wait_group %0;" :: "n"(n) : "memory")

// ---------------------------------------------------------------------------
// fp32 -> bf16 hi/lo split conversion
// ---------------------------------------------------------------------------
__global__ __launch_bounds__(256) void cvt_split_kernel(const float* __restrict__ in,
                                                        __nv_bfloat16* __restrict__ hi,
                                                        __nv_bfloat16* __restrict__ lo,
                                                        int n4)
{
    const int i = blockIdx.x * blockDim.x + threadIdx.x;
    if (i >= n4) return;
    const float4 v = ((const float4*)in)[i];
    union { __nv_bfloat16 b[4]; uint2 u; } H, L;
    const float vv[4] = {v.x, v.y, v.z, v.w};
#pragma unroll
    for (int j = 0; j < 4; j++) {
        H.b[j] = __float2bfloat16(vv[j]);
        L.b[j] = __float2bfloat16(vv[j] - __bfloat162float(H.b[j]));
    }
    ((uint2*)hi)[i] = H.u;
    ((uint2*)lo)[i] = L.u;
}

// ---------------------------------------------------------------------------
// HMMA bf16x3 GEMM: out[M,N] = A[M,K] @ W[N,K]^T + bias
// 128x128 CTA tile, BK=32, 8 warps (2x4) each computing 64x32.
// SMEM tile: 128 rows x 128B; row = [hi 4x16B | lo 4x16B], chunk^(row&7) swizzle.
// Double-buffered via cp.async. 3 mma passes: Ah*Bh + Ah*Bl + Al*Bh.
// ---------------------------------------------------------------------------
constexpr int BKg = 32;
constexpr int NKC = Dm / BKg;          // 32 k-chunks
constexpr int TILE_BYTES = 128 * 128;  // 16 KB (hi+lo combined)
constexpr int STAGE_BYTES = 2 * TILE_BYTES;   // A tile + B tile
constexpr int GEMM_SMEM = 2 * STAGE_BYTES;    // 64 KB double-buffered

__device__ __forceinline__ uint32_t swz(int row, int chunk) {
    return (uint32_t)(row * 128 + ((chunk ^ (row & 7)) * 16));
}

template <bool SPLIT_HEADS>
__global__ __launch_bounds__(256) void hmma_gemm_kernel(
    const __nv_bfloat16* __restrict__ Ah, const __nv_bfloat16* __restrict__ Al,
    const __nv_bfloat16* __restrict__ Bh, const __nv_bfloat16* __restrict__ Bl,
    const float* __restrict__ bias, float* __restrict__ out)
{
    extern __shared__ char sm[];
    const uint32_t smb = smem_u32(sm);
    const int t    = threadIdx.x;
    const int wid  = t >> 5;
    const int lane = t & 31;
    const int m0   = blockIdx.y * 128;
    const int n0   = blockIdx.x * 128;
    const int wm   = (wid & 1) * 64;   // warp row offset within CTA tile
    const int wn   = (wid >> 1) * 32;  // warp col offset

    // cp.async stage loader: tile A at stage base, tile B at +TILE_BYTES.
    auto load_stage = [&](int s, int kc) {
        const uint32_t ab = smb + s * STAGE_BYTES;
        const uint32_t bb = ab + TILE_BYTES;
#pragma unroll
        for (int i = 0; i < 4; i++) {
            const int idx  = t + i * 256;      // 0..1023
            const int row  = idx >> 3;
            const int c    = idx & 7;
            const int kofs = kc * BKg + (c & 3) * 8;
            const __nv_bfloat16* sa = (c < 4 ? Ah : Al) + (size_t)(m0 + row) * Dm + kofs;
            cp16(ab + swz(row, c), sa);
            const __nv_bfloat16* sb = (c < 4 ? Bh : Bl) + (size_t)(n0 + row) * Dm + kofs;
            cp16(bb + swz(row, c), sb);
        }
        CP_COMMIT();
    };

    float acc[4][4][4];
#pragma unroll
    for (int i = 0; i < 4; i++)
#pragma unroll
        for (int j = 0; j < 4; j++)
#pragma unroll
            for (int r = 0; r < 4; r++) acc[i][j][r] = 0.0f;

    load_stage(0, 0);

    const int lrow = lane & 15;
    const int lsel = lane >> 4;

    for (int kc = 0; kc < NKC; kc++) {
        const int s = kc & 1;
        if (kc + 1 < NKC) {
            load_stage(s ^ 1, kc + 1);
            CP_WAIT(1);
        } else {
            CP_WAIT(0);
        }
        __syncthreads();

        const uint32_t ab = smb + s * STAGE_BYTES;
        const uint32_t bb = ab + TILE_BYTES;

#pragma unroll
        for (int k16 = 0; k16 < 2; k16++) {
            const int ch = k16 * 2 + lsel;       // hi chunk for this lane
            uint32_t a_h[4][4], a_l[4][4];
#pragma unroll
            for (int mt = 0; mt < 4; mt++) {
                const int row = wm + mt * 16 + lrow;
                ldm_x4(a_h[mt], ab + swz(row, ch));
                ldm_x4(a_l[mt], ab + swz(row, ch + 4));
            }
            uint32_t b_h[2][4], b_l[2][4];
#pragma unroll
            for (int nt = 0; nt < 2; nt++) {
                const int row = wn + nt * 16 + lrow;
                ldm_x4(b_h[nt], bb + swz(row, ch));
                ldm_x4(b_l[nt], bb + swz(row, ch + 4));
            }
#pragma unroll
            for (int mt = 0; mt < 4; mt++) {
#pragma unroll
                for (int n8 = 0; n8 < 4; n8++) {
                    const int nt = n8 >> 1, sl = n8 & 1;
                    mma16816(acc[mt][n8], a_h[mt], b_h[nt][sl], b_h[nt][sl + 2]);
                    mma16816(acc[mt][n8], a_h[mt], b_l[nt][sl], b_l[nt][sl + 2]);
                    mma16816(acc[mt][n8], a_l[mt], b_h[nt][sl], b_h[nt][sl + 2]);
                }
            }
        }
        __syncthreads();
    }

    // Epilogue: c frag mapping: c0,c1 -> (row, col..col+1); c2,c3 -> (row+8, ..)
#pragma unroll
    for (int mt = 0; mt < 4; mt++) {
#pragma unroll
        for (int n8 = 0; n8 < 4; n8++) {
            const int r0 = m0 + wm + mt * 16 + (lane >> 2);
            const int c0 = n0 + wn + n8 * 8 + (lane & 3) * 2;
#pragma unroll
            for (int half = 0; half < 2; half++) {
                const int m = r0 + half * 8;
                const int b_ = m / Sq;
                const int s_ = m % Sq;
                const float v0 = acc[mt][n8][half * 2 + 0] + bias[c0];
                const float v1 = acc[mt][n8][half * 2 + 1] + bias[c0 + 1];
                if (SPLIT_HEADS) {
                    const int h_ = c0 >> 6;
                    const int d_ = c0 & 63;
                    float* dst = out + (((size_t)(b_ * Hh + h_)) * Sq + s_) * HDd + d_;
                    dst[0] = v0; dst[1] = v1;     // d_ even, pair within head
                } else {
                    float* dst = out + (size_t)m * Dm + c0;
                    dst[0] = v0; dst[1] = v1;
                }
            }
        }
    }
}

// ---------------------------------------------------------------------------
// Flash attention (round-1 known-good): fp32 SIMT, 64-query tiles.
// ---------------------------------------------------------------------------
constexpr int QS_STRIDE = 68;
constexpr int SMEM_FLOATS = 64 * QS_STRIDE * 3 + 64 * 64;
constexpr int SMEM_BYTES  = SMEM_FLOATS * 4 + 64 * 4;

__global__ __launch_bounds__(256)
void flash_attn_kernel(const float* __restrict__ Qg,
                       const float* __restrict__ Kg,
                       const float* __restrict__ Vg,
                       const int*   __restrict__ maskg,
                       float* __restrict__ ctx)
{
    extern __shared__ float smf[];
    float* Qs = smf;
    float* Kt = Qs + 64 * QS_STRIDE;
    float* Vs = Kt + 64 * QS_STRIDE;
    float* Ps = Vs + 64 * 64;
    int*   msk = (int*)(Ps + 64 * QS_STRIDE);

    const int t  = threadIdx.x;
    const int qt = blockIdx.x;
    const int h  = blockIdx.y;
    const int b  = blockIdx.z;
    const int tc = t & 15;
    const int tr = t >> 4;
    const int r0 = tr * 4;
    const int c0 = tc * 4;

    const size_t head_base = ((size_t)(b * Hh + h)) * Sq * HDd;
    const float* Qp = Qg + head_base + (size_t)qt * 64 * HDd;

    for (int idx = t; idx < 64 * 16; idx += 256) {
        const int row = idx >> 4;
        const int c4  = (idx & 15) << 2;
        float4 qv = *(const float4*)(Qp + row * HDd + c4);
        qv.x *= 0.125f; qv.y *= 0.125f; qv.z *= 0.125f; qv.w *= 0.125f;
        *(float4*)&Qs[row * QS_STRIDE + c4] = qv;
    }

    float m_i[4], l_i[4], o[4][4];
#pragma unroll
    for (int i = 0; i < 4; i++) {
        m_i[i] = -INFINITY;
        l_i[i] = 0.0f;
#pragma unroll
        for (int j = 0; j < 4; j++) o[i][j] = 0.0f;
    }

    for (int kt2 = 0; kt2 <= qt; kt2++) {
        const float* Kp = Kg + head_base + (size_t)kt2 * 64 * HDd;
        const float* Vp = Vg + head_base + (size_t)kt2 * 64 * HDd;

        __syncthreads();
        for (int idx = t; idx < 64 * 16; idx += 256) {
            const int row = idx >> 4;
            const int c4  = (idx & 15) << 2;
            const float4 kv = *(const float4*)(Kp + row * HDd + c4);
            Kt[(c4 + 0) * QS_STRIDE + row] = kv.x;
            Kt[(c4 + 1) * QS_STRIDE + row] = kv.y;
            Kt[(c4 + 2) * QS_STRIDE + row] = kv.z;
            Kt[(c4 + 3) * QS_STRIDE + row] = kv.w;
            const float4 vv = *(const float4*)(Vp + row * HDd + c4);
            *(float4*)&Vs[row * 64 + c4] = vv;
        }
        if (t < 64) msk[t] = maskg[b * Sq + kt2 * 64 + t];
        __syncthreads();

        float s4[4][4];
#pragma unroll
        for (int i = 0; i < 4; i++)
#pragma unroll
            for (int j = 0; j < 4; j++) s4[i][j] = 0.0f;

#pragma unroll 4
        for (int d4 = 0; d4 < 64; d4 += 4) {
            const float4 k0 = *(const float4*)&Kt[(d4 + 0) * QS_STRIDE + c0];
            const float4 k1 = *(const float4*)&Kt[(d4 + 1) * QS_STRIDE + c0];
            const float4 k2 = *(const float4*)&Kt[(d4 + 2) * QS_STRIDE + c0];
            const float4 k3 = *(const float4*)&Kt[(d4 + 3) * QS_STRIDE + c0];
#pragma unroll
            for (int i = 0; i < 4; i++) {
                const float4 qv = *(const float4*)&Qs[(r0 + i) * QS_STRIDE + d4];
                s4[i][0] += qv.x * k0.x + qv.y * k1.x + qv.z * k2.x + qv.w * k3.x;
                s4[i][1] += qv.x * k0.y + qv.y * k1.y + qv.z * k2.y + qv.w * k3.y;
                s4[i][2] += qv.x * k0.z + qv.y * k1.z + qv.z * k2.z + qv.w * k3.z;
                s4[i][3] += qv.x * k0.w + qv.y * k1.w + qv.z * k2.w + qv.w * k3.w;
            }
        }

        const bool diag = (kt2 == qt);
#pragma unroll
        for (int i = 0; i < 4; i++) {
#pragma unroll
            for (int j = 0; j < 4; j++) {
                const int kj = c0 + j;
                if (msk[kj] == 0)               s4[i][j] = -1e9f;
                else if (diag && kj > (r0 + i)) s4[i][j] = -INFINITY;
            }
        }

#pragma unroll
        for (int i = 0; i < 4; i++) {
            float mloc = fmaxf(fmaxf(s4[i][0], s4[i][1]), fmaxf(s4[i][2], s4[i][3]));
#pragma unroll
            for (int off = 1; off < 16; off <<= 1)
                mloc = fmaxf(mloc, __shfl_xor_sync(0xffffffffu, mloc, off));
            const float mnew  = fmaxf(m_i[i], mloc);
            const float alpha = __expf(m_i[i] - mnew);
            const float p0 = __expf(s4[i][0] - mnew);
            const float p1 = __expf(s4[i][1] - mnew);
            const float p2 = __expf(s4[i][2] - mnew);
            const float p3 = __expf(s4[i][3] - mnew);
            float ls = p0 + p1 + p2 + p3;
#pragma unroll
            for (int off = 1; off < 16; off <<= 1)
                ls += __shfl_xor_sync(0xffffffffu, ls, off);
            l_i[i] = l_i[i] * alpha + ls;
            m_i[i] = mnew;
            o[i][0] *= alpha; o[i][1] *= alpha; o[i][2] *= alpha; o[i][3] *= alpha;
            float4 pv; pv.x = p0; pv.y = p1; pv.z = p2; pv.w = p3;
            *(float4*)&Ps[(r0 + i) * QS_STRIDE + c0] = pv;
        }
        __syncthreads();

#pragma unroll 4
        for (int c4 = 0; c4 < 64; c4 += 4) {
            const float4 v0 = *(const float4*)&Vs[(c4 + 0) * 64 + c0];
            const float4 v1 = *(const float4*)&Vs[(c4 + 1) * 64 + c0];
            const float4 v2 = *(const float4*)&Vs[(c4 + 2) * 64 + c0];
            const float4 v3 = *(const float4*)&Vs[(c4 + 3) * 64 + c0];
#pragma unroll
            for (int i = 0; i < 4; i++) {
                const float4 pv = *(const float4*)&Ps[(r0 + i) * QS_STRIDE + c4];
                o[i][0] += pv.x * v0.x + pv.y * v1.x + pv.z * v2.x + pv.w * v3.x;
                o[i][1] += pv.x * v0.y + pv.y * v1.y + pv.z * v2.y + pv.w * v3.y;
                o[i][2] += pv.x * v0.z + pv.y * v1.z + pv.z * v2.z + pv.w * v3.z;
                o[i][3] += pv.x * v0.w + pv.y * v1.w + pv.z * v2.w + pv.w * v3.w;
            }
        }
    }

#pragma unroll
    for (int i = 0; i < 4; i++) {
        const float inv = 1.0f / l_i[i];
        float4 ov;
        ov.x = o[i][0] * inv; ov.y = o[i][1] * inv;
        ov.z = o[i][2] * inv; ov.w = o[i][3] * inv;
        const size_t row = (size_t)b * Sq + qt * 64 + r0 + i;
        *(float4*)(ctx + row * Dm + h * HDd + c0) = ov;
    }
}

// ---------------------------------------------------------------------------
// Launch
// ---------------------------------------------------------------------------
extern "C" void kernel_launch(void* const* d_in, const int* in_sizes, int n_in,
                              void* d_out, int out_size)
{
    const float* x  = nullptr;
    const int*   am = nullptr;
    const float* Ws[4] = {nullptr, nullptr, nullptr, nullptr};
    const float* bs[4] = {nullptr, nullptr, nullptr, nullptr};
    int wi = 0, bi = 0;
    for (int i = 0; i < n_in; i++) {
        const long sz = in_sizes[i];
        if (sz == (long)Mtot * Dm)      x = (const float*)d_in[i];
        else if (sz == (long)Mtot)      am = (const int*)d_in[i];
        else if (sz == (long)Dm * Dm) { if (wi < 4) Ws[wi++] = (const float*)d_in[i]; }
        else if (sz == (long)Dm)      { if (bi < 4) bs[bi++] = (const float*)d_in[i]; }
    }

    float *qp, *kp, *vp, *cp;
    __nv_bfloat16 *xh, *xl, *ch, *cl, *wh, *wl;
    cudaGetSymbolAddress((void**)&qp, g_q);
    cudaGetSymbolAddress((void**)&kp, g_k);
    cudaGetSymbolAddress((void**)&vp, g_v);
    cudaGetSymbolAddress((void**)&cp, g_ctx);
    cudaGetSymbolAddress((void**)&xh, g_xh);
    cudaGetSymbolAddress((void**)&xl, g_xl);
    cudaGetSymbolAddress((void**)&ch, g_ch);
    cudaGetSymbolAddress((void**)&cl, g_cl);
    cudaGetSymbolAddress((void**)&wh, g_wh);
    cudaGetSymbolAddress((void**)&wl, g_wl);

    cudaFuncSetAttribute(flash_attn_kernel,
                         cudaFuncAttributeMaxDynamicSharedMemorySize, SMEM_BYTES);
    cudaFuncSetAttribute(hmma_gemm_kernel<true>,
                         cudaFuncAttributeMaxDynamicSharedMemorySize, GEMM_SMEM);
    cudaFuncSetAttribute(hmma_gemm_kernel<false>,
                         cudaFuncAttributeMaxDynamicSharedMemorySize, GEMM_SMEM);

    // Split inputs into bf16 hi/lo
    const int n4x = Mtot * Dm / 4;
    const int n4w = Dm * Dm / 4;
    cvt_split_kernel<<<(n4x + 255) / 256, 256>>>(x, xh, xl, n4x);
    for (int i = 0; i < 4; i++)
        cvt_split_kernel<<<(n4w + 255) / 256, 256>>>(Ws[i],
            wh + (size_t)i * Dm * Dm, wl + (size_t)i * Dm * Dm, n4w);

    // Q/K/V projections on HMMA tensor path
    const dim3 gg(Dm / 128, Mtot / 128);
    hmma_gemm_kernel<true><<<gg, 256, GEMM_SMEM>>>(xh, xl, wh + 0 * (size_t)Dm * Dm,
                                                   wl + 0 * (size_t)Dm * Dm, bs[0], qp);
    hmma_gemm_kernel<true><<<gg, 256, GEMM_SMEM>>>(xh, xl, wh + 1 * (size_t)Dm * Dm,
                                                   wl + 1 * (size_t)Dm * Dm, bs[1], kp);
    hmma_gemm_kernel<true><<<gg, 256, GEMM_SMEM>>>(xh, xl, wh + 2 * (size_t)Dm * Dm,
                                                   wl + 2 * (size_t)Dm * Dm, bs[2], vp);

    // Attention
    const dim3 ga(Sq / 64, Hh, Bc);
    flash_attn_kernel<<<ga, 256, SMEM_BYTES>>>(qp, kp, vp, am, cp);

    // Output projection
    cvt_split_kernel<<<(n4x + 255) / 256, 256>>>(cp, ch, cl, n4x);
    hmma_gemm_kernel<false><<<gg, 256, GEMM_SMEM>>>(ch, cl, wh + 3 * (size_t)Dm * Dm,
                                                    wl + 3 * (size_t)Dm * Dm, bs[3], (float*)d_out);
}

// round 4
// speedup vs baseline: 2.8676x; 1.7825x over previous
#include <cuda_runtime.h>
#include <cuda_bf16.h>
#include <math.h>
#include <stdint.h>

// Problem constants
constexpr int Bc  = 4;
constexpr int Sq  = 2048;
constexpr int Dm  = 1024;
constexpr int Hh  = 16;
constexpr int HDd = 64;
constexpr int Mtot = Bc * Sq;           // 8192

// Scratch (device globals: allocation-free per harness rules)
__device__ __nv_bfloat16 g_xh[(size_t)Mtot * Dm];
__device__ __nv_bfloat16 g_xl[(size_t)Mtot * Dm];
__device__ __nv_bfloat16 g_wh[(size_t)4 * Dm * Dm];
__device__ __nv_bfloat16 g_wl[(size_t)4 * Dm * Dm];
__device__ __nv_bfloat16 g_qh[(size_t)Mtot * Dm];
__device__ __nv_bfloat16 g_ql[(size_t)Mtot * Dm];
__device__ __nv_bfloat16 g_kh[(size_t)Mtot * Dm];
__device__ __nv_bfloat16 g_kl[(size_t)Mtot * Dm];
__device__ __nv_bfloat16 g_vh[(size_t)Mtot * Dm];
__device__ __nv_bfloat16 g_vl[(size_t)Mtot * Dm];
__device__ __nv_bfloat16 g_ch[(size_t)Mtot * Dm];
__device__ __nv_bfloat16 g_cl[(size_t)Mtot * Dm];

// ---------------------------------------------------------------------------
// PTX helpers (sm_80-compatible subset: ldmatrix / mma.sync / cp.async)
// ---------------------------------------------------------------------------
__device__ __forceinline__ uint32_t smem_u32(const void* p) {
    uint32_t a;
    asm("{ .reg .u64 t; cvta.to.shared.u64 t, %1; cvt.u32.u64 %0, t; }" : "=r"(a) : "l"(p));
    return a;
}
__device__ __forceinline__ void ldm_x4(uint32_t (&r)[4], uint32_t saddr) {
    asm volatile("ldmatrix.sync.aligned.m8n8.x4.shared.b16 {%0,%1,%2,%3}, [%4];"
        : "=r"(r[0]), "=r"(r[1]), "=r"(r[2]), "=r"(r[3]) : "r"(saddr));
}
__device__ __forceinline__ void ldm_x4_t(uint32_t (&r)[4], uint32_t saddr) {
    asm volatile("ldmatrix.sync.aligned.m8n8.x4.trans.shared.b16 {%0,%1,%2,%3}, [%4];"
        : "=r"(r[0]), "=r"(r[1]), "=r"(r[2]), "=r"(r[3]) : "r"(saddr));
}
__device__ __forceinline__ void mma16816(float (&c)[4], const uint32_t (&a)[4],
                                         uint32_t b0, uint32_t b1) {
    asm volatile("mma.sync.aligned.m16n8k16.row.col.f32.bf16.bf16.f32 "
        "{%0,%1,%2,%3}, {%4,%5,%6,%7}, {%8,%9}, {%0,%1,%2,%3};"
        : "+f"(c[0]), "+f"(c[1]), "+f"(c[2]), "+f"(c[3])
        : "r"(a[0]), "r"(a[1]), "r"(a[2]), "r"(a[3]), "r"(b0), "r"(b1));
}
__device__ __forceinline__ void cp16(uint32_t dst, const void* src) {
    asm volatile("cp.async.cg.shared.global [%0], [%1], 16;" :: "r"(dst), "l"(src) : "memory");
}
#define CP_COMMIT() asm volatile("cp.async.commit_group;" ::: "memory")
#define CP_WAIT(n)  asm volatile("cp.async.wait_group %0;" :: "n"(n) : "memory")

__device__ __forceinline__ uint32_t bf2(float a, float b) {
    __nv_bfloat162 t = __floats2bfloat162_rn(a, b);
    return *reinterpret_cast<uint32_t*>(&t);
}
__device__ __forceinline__ float bf16rt(float a) {
    return __bfloat162float(__float2bfloat16(a));
}
__device__ __forceinline__ uint32_t swz(int row, int chunk) {
    return (uint32_t)(row * 128 + ((chunk ^ (row & 7)) * 16));
}

// ---------------------------------------------------------------------------
// fp32 -> bf16 hi/lo split conversion
// ---------------------------------------------------------------------------
__global__ __launch_bounds__(256) void cvt_split_kernel(const float* __restrict__ in,
                                                        __nv_bfloat16* __restrict__ hi,
                                                        __nv_bfloat16* __restrict__ lo,
                                                        int n4)
{
    const int i = blockIdx.x * blockDim.x + threadIdx.x;
    if (i >= n4) return;
    const float4 v = ((const float4*)in)[i];
    union { __nv_bfloat16 b[4]; uint2 u; } H, L;
    const float vv[4] = {v.x, v.y, v.z, v.w};
#pragma unroll
    for (int j = 0; j < 4; j++) {
        H.b[j] = __float2bfloat16(vv[j]);
        L.b[j] = __float2bfloat16(vv[j] - __bfloat162float(H.b[j]));
    }
    ((uint2*)hi)[i] = H.u;
    ((uint2*)lo)[i] = L.u;
}

// ---------------------------------------------------------------------------
// HMMA bf16x3 GEMM: 128x128 CTA tile, BK=32, 8 warps (2x4), cp.async 2-stage.
// SPLIT=true: writes bf16 hi/lo in [B,H,S,HD] layout, scaled.
// SPLIT=false: writes f32 [M,N].
// ---------------------------------------------------------------------------
constexpr int BKg = 32;
constexpr int NKC = Dm / BKg;
constexpr int TILE_BYTES = 128 * 128;
constexpr int STAGE_BYTES = 2 * TILE_BYTES;
constexpr int GEMM_SMEM = 2 * STAGE_BYTES;

template <bool SPLIT>
__global__ __launch_bounds__(256) void hmma_gemm_kernel(
    const __nv_bfloat16* __restrict__ Ah, const __nv_bfloat16* __restrict__ Al,
    const __nv_bfloat16* __restrict__ Bh, const __nv_bfloat16* __restrict__ Bl,
    const float* __restrict__ bias, float* __restrict__ outF,
    __nv_bfloat16* __restrict__ outH, __nv_bfloat16* __restrict__ outL,
    float scale)
{
    extern __shared__ char sm[];
    const uint32_t smb = smem_u32(sm);
    const int t    = threadIdx.x;
    const int wid  = t >> 5;
    const int lane = t & 31;
    const int m0   = blockIdx.y * 128;
    const int n0   = blockIdx.x * 128;
    const int wm   = (wid & 1) * 64;
    const int wn   = (wid >> 1) * 32;

    auto load_stage = [&](int s, int kc) {
        const uint32_t ab = smb + s * STAGE_BYTES;
        const uint32_t bb = ab + TILE_BYTES;
#pragma unroll
        for (int i = 0; i < 4; i++) {
            const int idx  = t + i * 256;
            const int row  = idx >> 3;
            const int c    = idx & 7;
            const int kofs = kc * BKg + (c & 3) * 8;
            const __nv_bfloat16* sa = (c < 4 ? Ah : Al) + (size_t)(m0 + row) * Dm + kofs;
            cp16(ab + swz(row, c), sa);
            const __nv_bfloat16* sb = (c < 4 ? Bh : Bl) + (size_t)(n0 + row) * Dm + kofs;
            cp16(bb + swz(row, c), sb);
        }
        CP_COMMIT();
    };

    float acc[4][4][4];
#pragma unroll
    for (int i = 0; i < 4; i++)
#pragma unroll
        for (int j = 0; j < 4; j++)
#pragma unroll
            for (int r = 0; r < 4; r++) acc[i][j][r] = 0.0f;

    load_stage(0, 0);

    const int lrow = lane & 15;
    const int lsel = lane >> 4;

    for (int kc = 0; kc < NKC; kc++) {
        const int s = kc & 1;
        if (kc + 1 < NKC) {
            load_stage(s ^ 1, kc + 1);
            CP_WAIT(1);
        } else {
            CP_WAIT(0);
        }
        __syncthreads();

        const uint32_t ab = smb + s * STAGE_BYTES;
        const uint32_t bb = ab + TILE_BYTES;

#pragma unroll
        for (int k16 = 0; k16 < 2; k16++) {
            const int ch = k16 * 2 + lsel;
            uint32_t a_h[4][4], a_l[4][4];
#pragma unroll
            for (int mt = 0; mt < 4; mt++) {
                const int row = wm + mt * 16 + lrow;
                ldm_x4(a_h[mt], ab + swz(row, ch));
                ldm_x4(a_l[mt], ab + swz(row, ch + 4));
            }
            uint32_t b_h[2][4], b_l[2][4];
#pragma unroll
            for (int nt = 0; nt < 2; nt++) {
                const int row = wn + nt * 16 + lrow;
                ldm_x4(b_h[nt], bb + swz(row, ch));
                ldm_x4(b_l[nt], bb + swz(row, ch + 4));
            }
#pragma unroll
            for (int mt = 0; mt < 4; mt++) {
#pragma unroll
                for (int n8 = 0; n8 < 4; n8++) {
                    const int nt = n8 >> 1, sl = n8 & 1;
                    mma16816(acc[mt][n8], a_h[mt], b_h[nt][sl], b_h[nt][sl + 2]);
                    mma16816(acc[mt][n8], a_h[mt], b_l[nt][sl], b_l[nt][sl + 2]);
                    mma16816(acc[mt][n8], a_l[mt], b_h[nt][sl], b_h[nt][sl + 2]);
                }
            }
        }
        __syncthreads();
    }

#pragma unroll
    for (int mt = 0; mt < 4; mt++) {
#pragma unroll
        for (int n8 = 0; n8 < 4; n8++) {
            const int r0 = m0 + wm + mt * 16 + (lane >> 2);
            const int c0 = n0 + wn + n8 * 8 + (lane & 3) * 2;
#pragma unroll
            for (int half = 0; half < 2; half++) {
                const int m = r0 + half * 8;
                const int b_ = m / Sq;
                const int s_ = m % Sq;
                const float v0 = (acc[mt][n8][half * 2 + 0] + bias[c0]) * scale;
                const float v1 = (acc[mt][n8][half * 2 + 1] + bias[c0 + 1]) * scale;
                if (SPLIT) {
                    const int h_ = c0 >> 6;
                    const int d_ = c0 & 63;
                    const size_t off =
                        ((((size_t)(b_ * Hh + h_)) * Sq + s_) * HDd + d_) >> 1;
                    ((uint32_t*)outH)[off] = bf2(v0, v1);
                    ((uint32_t*)outL)[off] = bf2(v0 - bf16rt(v0), v1 - bf16rt(v1));
                } else {
                    float* dst = outF + (size_t)m * Dm + c0;
                    dst[0] = v0; dst[1] = v1;
                }
            }
        }
    }
}

// ---------------------------------------------------------------------------
// HMMA flash attention: CTA = (64 queries, head, batch), 4 warps x 16 rows.
// Q/K/V bf16 hi/lo, QK^T and PV via bf16x3 m16n8k16. cp.async 2-stage K/V.
// Output written as bf16 hi/lo ctx [B,S,D].
// ---------------------------------------------------------------------------
constexpr int FA_STAGE = 4 * 8192 + 256;          // Kh,Kl,Vh,Vl + mask
constexpr int FA_SMEM  = 16384 + 2 * FA_STAGE;    // Qh,Ql + 2 stages = 82432

__global__ __launch_bounds__(128) void fa_hmma_kernel(
    const __nv_bfloat16* __restrict__ Qh, const __nv_bfloat16* __restrict__ Ql,
    const __nv_bfloat16* __restrict__ Kh, const __nv_bfloat16* __restrict__ Kl,
    const __nv_bfloat16* __restrict__ Vh, const __nv_bfloat16* __restrict__ Vl,
    const int* __restrict__ maskg,
    __nv_bfloat16* __restrict__ Ch, __nv_bfloat16* __restrict__ Cl)
{
    extern __shared__ char sm[];
    const uint32_t smb = smem_u32(sm);
    const int t    = threadIdx.x;
    const int w    = t >> 5;
    const int lane = t & 31;
    const int qt   = blockIdx.x;
    const int h    = blockIdx.y;
    const int b    = blockIdx.z;
    const size_t hb = ((size_t)(b * Hh + h)) * Sq * HDd;

    const uint32_t qhb = smb;
    const uint32_t qlb = smb + 8192;

    // Load Q tile (group 0, together with first K/V stage)
    {
        const char* srcH = (const char*)(Qh + hb + (size_t)qt * 64 * HDd);
        const char* srcL = (const char*)(Ql + hb + (size_t)qt * 64 * HDd);
#pragma unroll
        for (int i = 0; i < 4; i++) {
            const int idx = t + i * 128;
            const int row = idx >> 3, c = idx & 7;
            cp16(qhb + swz(row, c), srcH + idx * 16);
            cp16(qlb + swz(row, c), srcL + idx * 16);
        }
    }
    auto load_kv = [&](int s, int kt2) {
        const uint32_t kb = smb + 16384 + s * FA_STAGE;
        const char* sKH = (const char*)(Kh + hb + (size_t)kt2 * 64 * HDd);
        const char* sKL = (const char*)(Kl + hb + (size_t)kt2 * 64 * HDd);
        const char* sVH = (const char*)(Vh + hb + (size_t)kt2 * 64 * HDd);
        const char* sVL = (const char*)(Vl + hb + (size_t)kt2 * 64 * HDd);
#pragma unroll
        for (int i = 0; i < 4; i++) {
            const int idx = t + i * 128;
            const int row = idx >> 3, c = idx & 7;
            cp16(kb + swz(row, c), sKH + idx * 16);
            cp16(kb + 8192  + swz(row, c), sKL + idx * 16);
            cp16(kb + 16384 + swz(row, c), sVH + idx * 16);
            cp16(kb + 24576 + swz(row, c), sVL + idx * 16);
        }
        if (t < 16) cp16(kb + 32768 + t * 16, maskg + b * Sq + kt2 * 64 + t * 4);
        CP_COMMIT();
    };
    load_kv(0, 0);

    const int lrow  = lane & 15;
    const int lsel  = lane >> 4;
    const int rl    = lane >> 2;         // local row 0..7
    const int cbase = (lane & 3) * 2;
    const int wr0   = w * 16;

    float m_i[2] = {-INFINITY, -INFINITY};
    float l_i[2] = {0.0f, 0.0f};
    float o[8][4];
#pragma unroll
    for (int n8 = 0; n8 < 8; n8++)
#pragma unroll
        for (int c = 0; c < 4; c++) o[n8][c] = 0.0f;

    for (int kt2 = 0; kt2 <= qt; kt2++) {
        const int s = kt2 & 1;
        if (kt2 < qt) { load_kv(s ^ 1, kt2 + 1); CP_WAIT(1); }
        else          { CP_WAIT(0); }
        __syncthreads();

        const uint32_t kb  = smb + 16384 + s * FA_STAGE;
        const uint32_t khb = kb, klb = kb + 8192, vhb = kb + 16384, vlb = kb + 24576;
        const int* msk = (const int*)(sm + 16384 + s * FA_STAGE + 32768);

        // ---- S = Q @ K^T (bf16x3) ----
        float sc[8][4];
#pragma unroll
        for (int n8 = 0; n8 < 8; n8++)
#pragma unroll
            for (int c = 0; c < 4; c++) sc[n8][c] = 0.0f;

#pragma unroll
        for (int k16 = 0; k16 < 4; k16++) {
            const int ch = k16 * 2 + lsel;
            uint32_t qf_h[4], qf_l[4];
            ldm_x4(qf_h, qhb + swz(wr0 + lrow, ch));
            ldm_x4(qf_l, qlb + swz(wr0 + lrow, ch));
            uint32_t kf_h[4][4], kf_l[4][4];
#pragma unroll
            for (int nt = 0; nt < 4; nt++) {
                ldm_x4(kf_h[nt], khb + swz(nt * 16 + lrow, ch));
                ldm_x4(kf_l[nt], klb + swz(nt * 16 + lrow, ch));
            }
#pragma unroll
            for (int n8 = 0; n8 < 8; n8++) {
                const int nt = n8 >> 1, sl = n8 & 1;
                mma16816(sc[n8], qf_h, kf_h[nt][sl], kf_h[nt][sl + 2]);
                mma16816(sc[n8], qf_h, kf_l[nt][sl], kf_l[nt][sl + 2]);
                mma16816(sc[n8], qf_l, kf_h[nt][sl], kf_h[nt][sl + 2]);
            }
        }

        // ---- masking (pad overrides causal, reference order) ----
        const bool diag = (kt2 == qt);
        const int qi0 = qt * 64 + wr0 + rl;
#pragma unroll
        for (int n8 = 0; n8 < 8; n8++) {
#pragma unroll
            for (int c = 0; c < 4; c++) {
                const int colL = n8 * 8 + cbase + (c & 1);
                const int mv = msk[colL];
                if (mv == 0) sc[n8][c] = -1e9f;
                else if (diag) {
                    const int kj = kt2 * 64 + colL;
                    const int qi = qi0 + (c >> 1) * 8;
                    if (kj > qi) sc[n8][c] = -INFINITY;
                }
            }
        }

        // ---- online softmax (rows rl, rl+8) ----
#pragma unroll
        for (int r = 0; r < 2; r++) {
            float mx = -INFINITY;
#pragma unroll
            for (int n8 = 0; n8 < 8; n8++)
                mx = fmaxf(mx, fmaxf(sc[n8][2 * r], sc[n8][2 * r + 1]));
            mx = fmaxf(mx, __shfl_xor_sync(0xffffffffu, mx, 1));
            mx = fmaxf(mx, __shfl_xor_sync(0xffffffffu, mx, 2));
            const float mnew  = fmaxf(m_i[r], mx);
            const float alpha = __expf(m_i[r] - mnew);
            float sum = 0.0f;
#pragma unroll
            for (int n8 = 0; n8 < 8; n8++) {
                const float p0 = __expf(sc[n8][2 * r]     - mnew);
                const float p1 = __expf(sc[n8][2 * r + 1] - mnew);
                sc[n8][2 * r] = p0; sc[n8][2 * r + 1] = p1;
                sum += p0 + p1;
            }
            sum += __shfl_xor_sync(0xffffffffu, sum, 1);
            sum += __shfl_xor_sync(0xffffffffu, sum, 2);
            l_i[r] = l_i[r] * alpha + sum;
            m_i[r] = mnew;
#pragma unroll
            for (int n8 = 0; n8 < 8; n8++) {
                o[n8][2 * r] *= alpha; o[n8][2 * r + 1] *= alpha;
            }
        }

        // ---- P -> bf16 hi/lo A-fragments ----
        uint32_t pah[4][4], pal[4][4];
#pragma unroll
        for (int j = 0; j < 4; j++) {
#pragma unroll
            for (int u = 0; u < 4; u++) {
                const int tile = 2 * j + (u >> 1);
                const int ci   = (u & 1) * 2;
                const float p0 = sc[tile][ci], p1 = sc[tile][ci + 1];
                pah[j][u] = bf2(p0, p1);
                pal[j][u] = bf2(p0 - bf16rt(p0), p1 - bf16rt(p1));
            }
        }

        // ---- O += P @ V (bf16x3), V via ldmatrix.trans ----
#pragma unroll
        for (int j = 0; j < 4; j++) {
            const int mrow = 16 * j + ((lane >> 3) & 1) * 8 + (lane & 7);
            uint32_t vf_h[4][4], vf_l[4][4];
#pragma unroll
            for (int hp = 0; hp < 4; hp++) {
                const int chv = hp * 2 + (lane >> 4);
                ldm_x4_t(vf_h[hp], vhb + swz(mrow, chv));
                ldm_x4_t(vf_l[hp], vlb + swz(mrow, chv));
            }
#pragma unroll
            for (int n8 = 0; n8 < 8; n8++) {
                const int hp = n8 >> 1, q_ = n8 & 1;
                mma16816(o[n8], pah[j], vf_h[hp][2 * q_], vf_h[hp][2 * q_ + 1]);
                mma16816(o[n8], pal[j], vf_h[hp][2 * q_], vf_h[hp][2 * q_ + 1]);
                mma16816(o[n8], pah[j], vf_l[hp][2 * q_], vf_l[hp][2 * q_ + 1]);
            }
        }
        __syncthreads();
    }

    // ---- normalize + write ctx hi/lo [B,S,D] ----
#pragma unroll
    for (int r = 0; r < 2; r++) {
        const float inv = 1.0f / l_i[r];
        const int m = qt * 64 + wr0 + rl + r * 8;
        const size_t rowoff = ((size_t)b * Sq + m) * Dm + h * HDd;
#pragma unroll
        for (int n8 = 0; n8 < 8; n8++) {
            const int col = n8 * 8 + cbase;
            const float v0 = o[n8][2 * r] * inv;
            const float v1 = o[n8][2 * r + 1] * inv;
            ((uint32_t*)(Ch + rowoff + col))[0] = bf2(v0, v1);
            ((uint32_t*)(Cl + rowoff + col))[0] =
                bf2(v0 - bf16rt(v0), v1 - bf16rt(v1));
        }
    }
}

// ---------------------------------------------------------------------------
// Launch
// ---------------------------------------------------------------------------
extern "C" void kernel_launch(void* const* d_in, const int* in_sizes, int n_in,
                              void* d_out, int out_size)
{
    const float* x  = nullptr;
    const int*   am = nullptr;
    const float* Ws[4] = {nullptr, nullptr, nullptr, nullptr};
    const float* bs[4] = {nullptr, nullptr, nullptr, nullptr};
    int wi = 0, bi = 0;
    for (int i = 0; i < n_in; i++) {
        const long sz = in_sizes[i];
        if (sz == (long)Mtot * Dm)      x = (const float*)d_in[i];
        else if (sz == (long)Mtot)      am = (const int*)d_in[i];
        else if (sz == (long)Dm * Dm) { if (wi < 4) Ws[wi++] = (const float*)d_in[i]; }
        else if (sz == (long)Dm)      { if (bi < 4) bs[bi++] = (const float*)d_in[i]; }
    }

    __nv_bfloat16 *xh, *xl, *wh, *wl, *qh, *ql, *kh, *kl, *vh, *vl, *ch, *cl;
    cudaGetSymbolAddress((void**)&xh, g_xh);
    cudaGetSymbolAddress((void**)&xl, g_xl);
    cudaGetSymbolAddress((void**)&wh, g_wh);
    cudaGetSymbolAddress((void**)&wl, g_wl);
    cudaGetSymbolAddress((void**)&qh, g_qh);
    cudaGetSymbolAddress((void**)&ql, g_ql);
    cudaGetSymbolAddress((void**)&kh, g_kh);
    cudaGetSymbolAddress((void**)&kl, g_kl);
    cudaGetSymbolAddress((void**)&vh, g_vh);
    cudaGetSymbolAddress((void**)&vl, g_vl);
    cudaGetSymbolAddress((void**)&ch, g_ch);
    cudaGetSymbolAddress((void**)&cl, g_cl);

    cudaFuncSetAttribute(hmma_gemm_kernel<true>,
                         cudaFuncAttributeMaxDynamicSharedMemorySize, GEMM_SMEM);
    cudaFuncSetAttribute(hmma_gemm_kernel<false>,
                         cudaFuncAttributeMaxDynamicSharedMemorySize, GEMM_SMEM);
    cudaFuncSetAttribute(fa_hmma_kernel,
                         cudaFuncAttributeMaxDynamicSharedMemorySize, FA_SMEM);

    // Split inputs into bf16 hi/lo
    const int n4x = Mtot * Dm / 4;
    const int n4w = Dm * Dm / 4;
    cvt_split_kernel<<<(n4x + 255) / 256, 256>>>(x, xh, xl, n4x);
    for (int i = 0; i < 4; i++)
        cvt_split_kernel<<<(n4w + 255) / 256, 256>>>(Ws[i],
            wh + (size_t)i * Dm * Dm, wl + (size_t)i * Dm * Dm, n4w);

    // Q/K/V projections (Q carries softmax scale, exact power of 2)
    const dim3 gg(Dm / 128, Mtot / 128);
    hmma_gemm_kernel<true><<<gg, 256, GEMM_SMEM>>>(
        xh, xl, wh + 0 * (size_t)Dm * Dm, wl + 0 * (size_t)Dm * Dm, bs[0],
        nullptr, qh, ql, 0.125f);
    hmma_gemm_kernel<true><<<gg, 256, GEMM_SMEM>>>(
        xh, xl, wh + 1 * (size_t)Dm * Dm, wl + 1 * (size_t)Dm * Dm, bs[1],
        nullptr, kh, kl, 1.0f);
    hmma_gemm_kernel<true><<<gg, 256, GEMM_SMEM>>>(
        xh, xl, wh + 2 * (size_t)Dm * Dm, wl + 2 * (size_t)Dm * Dm, bs[2],
        nullptr, vh, vl, 1.0f);

    // Attention (HMMA)
    const dim3 ga(Sq / 64, Hh, Bc);
    fa_hmma_kernel<<<ga, 128, FA_SMEM>>>(qh, ql, kh, kl, vh, vl, am, ch, cl);

    // Output projection
    hmma_gemm_kernel<false><<<gg, 256, GEMM_SMEM>>>(
        ch, cl, wh + 3 * (size_t)Dm * Dm, wl + 3 * (size_t)Dm * Dm, bs[3],
        (float*)d_out, nullptr, nullptr, 1.0f);
}

// round 5
// speedup vs baseline: 3.0259x; 1.0552x over previous
#include <cuda_runtime.h>
#include <cuda_bf16.h>
#include <math.h>
#include <stdint.h>

// Problem constants
constexpr int Bc  = 4;
constexpr int Sq  = 2048;
constexpr int Dm  = 1024;
constexpr int Hh  = 16;
constexpr int HDd = 64;
constexpr int Mtot = Bc * Sq;           // 8192

// Scratch (device globals: allocation-free per harness rules)
__device__ __nv_bfloat16 g_xh[(size_t)Mtot * Dm];
__device__ __nv_bfloat16 g_xl[(size_t)Mtot * Dm];
__device__ __nv_bfloat16 g_wh[(size_t)4 * Dm * Dm];
__device__ __nv_bfloat16 g_wl[(size_t)4 * Dm * Dm];
__device__ __nv_bfloat16 g_qh[(size_t)Mtot * Dm];
__device__ __nv_bfloat16 g_ql[(size_t)Mtot * Dm];
__device__ __nv_bfloat16 g_kh[(size_t)Mtot * Dm];
__device__ __nv_bfloat16 g_kl[(size_t)Mtot * Dm];
__device__ __nv_bfloat16 g_vh[(size_t)Mtot * Dm];
__device__ __nv_bfloat16 g_vl[(size_t)Mtot * Dm];
__device__ __nv_bfloat16 g_ch[(size_t)Mtot * Dm];
__device__ __nv_bfloat16 g_cl[(size_t)Mtot * Dm];

// ---------------------------------------------------------------------------
// PTX helpers (sm_80-compatible subset: ldmatrix / mma.sync / cp.async)
// ---------------------------------------------------------------------------
__device__ __forceinline__ uint32_t smem_u32(const void* p) {
    uint32_t a;
    asm("{ .reg .u64 t; cvta.to.shared.u64 t, %1; cvt.u32.u64 %0, t; }" : "=r"(a) : "l"(p));
    return a;
}
__device__ __forceinline__ void ldm_x4(uint32_t (&r)[4], uint32_t saddr) {
    asm volatile("ldmatrix.sync.aligned.m8n8.x4.shared.b16 {%0,%1,%2,%3}, [%4];"
        : "=r"(r[0]), "=r"(r[1]), "=r"(r[2]), "=r"(r[3]) : "r"(saddr));
}
__device__ __forceinline__ void ldm_x4_t(uint32_t (&r)[4], uint32_t saddr) {
    asm volatile("ldmatrix.sync.aligned.m8n8.x4.trans.shared.b16 {%0,%1,%2,%3}, [%4];"
        : "=r"(r[0]), "=r"(r[1]), "=r"(r[2]), "=r"(r[3]) : "r"(saddr));
}
__device__ __forceinline__ void mma16816(float (&c)[4], const uint32_t (&a)[4],
                                         uint32_t b0, uint32_t b1) {
    asm volatile("mma.sync.aligned.m16n8k16.row.col.f32.bf16.bf16.f32 "
        "{%0,%1,%2,%3}, {%4,%5,%6,%7}, {%8,%9}, {%0,%1,%2,%3};"
        : "+f"(c[0]), "+f"(c[1]), "+f"(c[2]), "+f"(c[3])
        : "r"(a[0]), "r"(a[1]), "r"(a[2]), "r"(a[3]), "r"(b0), "r"(b1));
}
__device__ __forceinline__ void cp16(uint32_t dst, const void* src) {
    asm volatile("cp.async.cg.shared.global [%0], [%1], 16;" :: "r"(dst), "l"(src) : "memory");
}
#define CP_COMMIT() asm volatile("cp.async.commit_group;" ::: "memory")
#define CP_WAIT(n)  asm volatile("cp.async.wait_group %0;" :: "n"(n) : "memory")

__device__ __forceinline__ uint32_t bf2(float a, float b) {
    __nv_bfloat162 t = __floats2bfloat162_rn(a, b);
    return *reinterpret_cast<uint32_t*>(&t);
}
__device__ __forceinline__ float bf16rt(float a) {
    return __bfloat162float(__float2bfloat16(a));
}
__device__ __forceinline__ uint32_t swz(int row, int chunk) {
    return (uint32_t)(row * 128 + ((chunk ^ (row & 7)) * 16));
}

// ---------------------------------------------------------------------------
// fp32 -> bf16 hi/lo split conversion (x: 1D grid; weights: y-indexed 4x)
// ---------------------------------------------------------------------------
__global__ __launch_bounds__(256) void cvt_split_kernel(const float* __restrict__ in,
                                                        __nv_bfloat16* __restrict__ hi,
                                                        __nv_bfloat16* __restrict__ lo,
                                                        int n4)
{
    const int i = blockIdx.x * blockDim.x + threadIdx.x;
    if (i >= n4) return;
    const float4 v = ((const float4*)in)[i];
    union { __nv_bfloat16 b[4]; uint2 u; } H, L;
    const float vv[4] = {v.x, v.y, v.z, v.w};
#pragma unroll
    for (int j = 0; j < 4; j++) {
        H.b[j] = __float2bfloat16(vv[j]);
        L.b[j] = __float2bfloat16(vv[j] - __bfloat162float(H.b[j]));
    }
    ((uint2*)hi)[i] = H.u;
    ((uint2*)lo)[i] = L.u;
}

__global__ __launch_bounds__(256) void cvt_split_w_kernel(
    const float* __restrict__ w0, const float* __restrict__ w1,
    const float* __restrict__ w2, const float* __restrict__ w3,
    __nv_bfloat16* __restrict__ hi, __nv_bfloat16* __restrict__ lo)
{
    const int n4 = Dm * Dm / 4;
    const int i = blockIdx.x * blockDim.x + threadIdx.x;
    if (i >= n4) return;
    const int wsel = blockIdx.y;
    const float* in = wsel == 0 ? w0 : wsel == 1 ? w1 : wsel == 2 ? w2 : w3;
    const size_t off = (size_t)wsel * n4 + i;
    const float4 v = ((const float4*)in)[i];
    union { __nv_bfloat16 b[4]; uint2 u; } H, L;
    const float vv[4] = {v.x, v.y, v.z, v.w};
#pragma unroll
    for (int j = 0; j < 4; j++) {
        H.b[j] = __float2bfloat16(vv[j]);
        L.b[j] = __float2bfloat16(vv[j] - __bfloat162float(H.b[j]));
    }
    ((uint2*)hi)[off] = H.u;
    ((uint2*)lo)[off] = L.u;
}

// ---------------------------------------------------------------------------
// HMMA bf16x3 GEMM: 128x128 CTA tile, BK=32, 8 warps (2x4), cp.async 3-stage.
// blockIdx.z selects among up to 3 (W, bias, out) sets (fused Q/K/V).
// SPLIT=true: writes bf16 hi/lo in [B,H,S,HD]; SPLIT=false: f32 [M,N].
// ---------------------------------------------------------------------------
constexpr int BKg = 32;
constexpr int NKC = Dm / BKg;
constexpr int TILE_BYTES = 128 * 128;
constexpr int STAGE_BYTES = 2 * TILE_BYTES;     // 32 KB (A + B tiles)
constexpr int GEMM_SMEM = 3 * STAGE_BYTES;      // 96 KB, 3-stage ring

template <bool SPLIT>
__global__ __launch_bounds__(256) void hmma_gemm_kernel(
    const __nv_bfloat16* __restrict__ Ah, const __nv_bfloat16* __restrict__ Al,
    const __nv_bfloat16* __restrict__ Bh0, const __nv_bfloat16* __restrict__ Bh1,
    const __nv_bfloat16* __restrict__ Bh2,
    const __nv_bfloat16* __restrict__ Bl0, const __nv_bfloat16* __restrict__ Bl1,
    const __nv_bfloat16* __restrict__ Bl2,
    const float* __restrict__ bias0, const float* __restrict__ bias1,
    const float* __restrict__ bias2,
    float* __restrict__ outF,
    __nv_bfloat16* __restrict__ oh0, __nv_bfloat16* __restrict__ oh1,
    __nv_bfloat16* __restrict__ oh2,
    __nv_bfloat16* __restrict__ ol0, __nv_bfloat16* __restrict__ ol1,
    __nv_bfloat16* __restrict__ ol2)
{
    extern __shared__ char sm[];
    const uint32_t smb = smem_u32(sm);
    const int z    = blockIdx.z;
    const __nv_bfloat16* Bh = z == 0 ? Bh0 : z == 1 ? Bh1 : Bh2;
    const __nv_bfloat16* Bl = z == 0 ? Bl0 : z == 1 ? Bl1 : Bl2;
    const float* bias       = z == 0 ? bias0 : z == 1 ? bias1 : bias2;
    __nv_bfloat16* outH     = z == 0 ? oh0 : z == 1 ? oh1 : oh2;
    __nv_bfloat16* outL     = z == 0 ? ol0 : z == 1 ? ol1 : ol2;
    const float scale = (SPLIT && z == 0) ? 0.125f : 1.0f;

    const int t    = threadIdx.x;
    const int wid  = t >> 5;
    const int lane = t & 31;
    const int m0   = blockIdx.y * 128;
    const int n0   = blockIdx.x * 128;
    const int wm   = (wid & 1) * 64;
    const int wn   = (wid >> 1) * 32;

    auto load_stage = [&](int s, int kc) {
        const uint32_t ab = smb + s * STAGE_BYTES;
        const uint32_t bb = ab + TILE_BYTES;
#pragma unroll
        for (int i = 0; i < 4; i++) {
            const int idx  = t + i * 256;
            const int row  = idx >> 3;
            const int c    = idx & 7;
            const int kofs = kc * BKg + (c & 3) * 8;
            const __nv_bfloat16* sa = (c < 4 ? Ah : Al) + (size_t)(m0 + row) * Dm + kofs;
            cp16(ab + swz(row, c), sa);
            const __nv_bfloat16* sb = (c < 4 ? Bh : Bl) + (size_t)(n0 + row) * Dm + kofs;
            cp16(bb + swz(row, c), sb);
        }
        CP_COMMIT();
    };

    float acc[4][4][4];
#pragma unroll
    for (int i = 0; i < 4; i++)
#pragma unroll
        for (int j = 0; j < 4; j++)
#pragma unroll
            for (int r = 0; r < 4; r++) acc[i][j][r] = 0.0f;

    load_stage(0, 0);
    load_stage(1, 1);

    const int lrow = lane & 15;
    const int lsel = lane >> 4;

    int s = 0;
    for (int kc = 0; kc < NKC; kc++) {
        if (kc + 1 < NKC) { CP_WAIT(1); } else { CP_WAIT(0); }
        __syncthreads();
        if (kc + 2 < NKC) {
            int s2 = s + 2; if (s2 >= 3) s2 -= 3;
            load_stage(s2, kc + 2);
        }

        const uint32_t ab = smb + s * STAGE_BYTES;
        const uint32_t bb = ab + TILE_BYTES;

#pragma unroll
        for (int k16 = 0; k16 < 2; k16++) {
            const int ch = k16 * 2 + lsel;
            uint32_t a_h[4][4], a_l[4][4];
#pragma unroll
            for (int mt = 0; mt < 4; mt++) {
                const int row = wm + mt * 16 + lrow;
                ldm_x4(a_h[mt], ab + swz(row, ch));
                ldm_x4(a_l[mt], ab + swz(row, ch + 4));
            }
            uint32_t b_h[2][4], b_l[2][4];
#pragma unroll
            for (int nt = 0; nt < 2; nt++) {
                const int row = wn + nt * 16 + lrow;
                ldm_x4(b_h[nt], bb + swz(row, ch));
                ldm_x4(b_l[nt], bb + swz(row, ch + 4));
            }
#pragma unroll
            for (int mt = 0; mt < 4; mt++) {
#pragma unroll
                for (int n8 = 0; n8 < 4; n8++) {
                    const int nt = n8 >> 1, sl = n8 & 1;
                    mma16816(acc[mt][n8], a_h[mt], b_h[nt][sl], b_h[nt][sl + 2]);
                    mma16816(acc[mt][n8], a_h[mt], b_l[nt][sl], b_l[nt][sl + 2]);
                    mma16816(acc[mt][n8], a_l[mt], b_h[nt][sl], b_h[nt][sl + 2]);
                }
            }
        }
        if (++s == 3) s = 0;
    }

#pragma unroll
    for (int mt = 0; mt < 4; mt++) {
#pragma unroll
        for (int n8 = 0; n8 < 4; n8++) {
            const int r0 = m0 + wm + mt * 16 + (lane >> 2);
            const int c0 = n0 + wn + n8 * 8 + (lane & 3) * 2;
#pragma unroll
            for (int half = 0; half < 2; half++) {
                const int m = r0 + half * 8;
                const int b_ = m / Sq;
                const int s_ = m % Sq;
                const float v0 = (acc[mt][n8][half * 2 + 0] + bias[c0]) * scale;
                const float v1 = (acc[mt][n8][half * 2 + 1] + bias[c0 + 1]) * scale;
                if (SPLIT) {
                    const int h_ = c0 >> 6;
                    const int d_ = c0 & 63;
                    const size_t off =
                        ((((size_t)(b_ * Hh + h_)) * Sq + s_) * HDd + d_) >> 1;
                    ((uint32_t*)outH)[off] = bf2(v0, v1);
                    ((uint32_t*)outL)[off] = bf2(v0 - bf16rt(v0), v1 - bf16rt(v1));
                } else {
                    float* dst = outF + (size_t)m * Dm + c0;
                    dst[0] = v0; dst[1] = v1;
                }
            }
        }
    }
}

// ---------------------------------------------------------------------------
// HMMA flash attention: CTA = (64 queries, head, batch), 4 warps x 16 rows.
// ---------------------------------------------------------------------------
constexpr int FA_STAGE = 4 * 8192 + 256;          // Kh,Kl,Vh,Vl + mask
constexpr int FA_SMEM  = 16384 + 2 * FA_STAGE;    // Qh,Ql + 2 stages = 82432

__global__ __launch_bounds__(128) void fa_hmma_kernel(
    const __nv_bfloat16* __restrict__ Qh, const __nv_bfloat16* __restrict__ Ql,
    const __nv_bfloat16* __restrict__ Kh, const __nv_bfloat16* __restrict__ Kl,
    const __nv_bfloat16* __restrict__ Vh, const __nv_bfloat16* __restrict__ Vl,
    const int* __restrict__ maskg,
    __nv_bfloat16* __restrict__ Ch, __nv_bfloat16* __restrict__ Cl)
{
    extern __shared__ char sm[];
    const uint32_t smb = smem_u32(sm);
    const int t    = threadIdx.x;
    const int w    = t >> 5;
    const int lane = t & 31;
    const int qt   = blockIdx.x;
    const int h    = blockIdx.y;
    const int b    = blockIdx.z;
    const size_t hb = ((size_t)(b * Hh + h)) * Sq * HDd;

    const uint32_t qhb = smb;
    const uint32_t qlb = smb + 8192;

    {
        const char* srcH = (const char*)(Qh + hb + (size_t)qt * 64 * HDd);
        const char* srcL = (const char*)(Ql + hb + (size_t)qt * 64 * HDd);
#pragma unroll
        for (int i = 0; i < 4; i++) {
            const int idx = t + i * 128;
            const int row = idx >> 3, c = idx & 7;
            cp16(qhb + swz(row, c), srcH + idx * 16);
            cp16(qlb + swz(row, c), srcL + idx * 16);
        }
    }
    auto load_kv = [&](int s, int kt2) {
        const uint32_t kb = smb + 16384 + s * FA_STAGE;
        const char* sKH = (const char*)(Kh + hb + (size_t)kt2 * 64 * HDd);
        const char* sKL = (const char*)(Kl + hb + (size_t)kt2 * 64 * HDd);
        const char* sVH = (const char*)(Vh + hb + (size_t)kt2 * 64 * HDd);
        const char* sVL = (const char*)(Vl + hb + (size_t)kt2 * 64 * HDd);
#pragma unroll
        for (int i = 0; i < 4; i++) {
            const int idx = t + i * 128;
            const int row = idx >> 3, c = idx & 7;
            cp16(kb + swz(row, c), sKH + idx * 16);
            cp16(kb + 8192  + swz(row, c), sKL + idx * 16);
            cp16(kb + 16384 + swz(row, c), sVH + idx * 16);
            cp16(kb + 24576 + swz(row, c), sVL + idx * 16);
        }
        if (t < 16) cp16(kb + 32768 + t * 16, maskg + b * Sq + kt2 * 64 + t * 4);
        CP_COMMIT();
    };
    load_kv(0, 0);

    const int lrow  = lane & 15;
    const int lsel  = lane >> 4;
    const int rl    = lane >> 2;
    const int cbase = (lane & 3) * 2;
    const int wr0   = w * 16;

    float m_i[2] = {-INFINITY, -INFINITY};
    float l_i[2] = {0.0f, 0.0f};
    float o[8][4];
#pragma unroll
    for (int n8 = 0; n8 < 8; n8++)
#pragma unroll
        for (int c = 0; c < 4; c++) o[n8][c] = 0.0f;

    for (int kt2 = 0; kt2 <= qt; kt2++) {
        const int s = kt2 & 1;
        if (kt2 < qt) { load_kv(s ^ 1, kt2 + 1); CP_WAIT(1); }
        else          { CP_WAIT(0); }
        __syncthreads();

        const uint32_t kb  = smb + 16384 + s * FA_STAGE;
        const uint32_t khb = kb, klb = kb + 8192, vhb = kb + 16384, vlb = kb + 24576;
        const int* msk = (const int*)(sm + 16384 + s * FA_STAGE + 32768);

        float sc[8][4];
#pragma unroll
        for (int n8 = 0; n8 < 8; n8++)
#pragma unroll
            for (int c = 0; c < 4; c++) sc[n8][c] = 0.0f;

#pragma unroll
        for (int k16 = 0; k16 < 4; k16++) {
            const int ch = k16 * 2 + lsel;
            uint32_t qf_h[4], qf_l[4];
            ldm_x4(qf_h, qhb + swz(wr0 + lrow, ch));
            ldm_x4(qf_l, qlb + swz(wr0 + lrow, ch));
            uint32_t kf_h[4][4], kf_l[4][4];
#pragma unroll
            for (int nt = 0; nt < 4; nt++) {
                ldm_x4(kf_h[nt], khb + swz(nt * 16 + lrow, ch));
                ldm_x4(kf_l[nt], klb + swz(nt * 16 + lrow, ch));
            }
#pragma unroll
            for (int n8 = 0; n8 < 8; n8++) {
                const int nt = n8 >> 1, sl = n8 & 1;
                mma16816(sc[n8], qf_h, kf_h[nt][sl], kf_h[nt][sl + 2]);
                mma16816(sc[n8], qf_h, kf_l[nt][sl], kf_l[nt][sl + 2]);
                mma16816(sc[n8], qf_l, kf_h[nt][sl], kf_h[nt][sl + 2]);
            }
        }

        const bool diag = (kt2 == qt);
        const int qi0 = qt * 64 + wr0 + rl;
#pragma unroll
        for (int n8 = 0; n8 < 8; n8++) {
#pragma unroll
            for (int c = 0; c < 4; c++) {
                const int colL = n8 * 8 + cbase + (c & 1);
                const int mv = msk[colL];
                if (mv == 0) sc[n8][c] = -1e9f;
                else if (diag) {
                    const int kj = kt2 * 64 + colL;
                    const int qi = qi0 + (c >> 1) * 8;
                    if (kj > qi) sc[n8][c] = -INFINITY;
                }
            }
        }

#pragma unroll
        for (int r = 0; r < 2; r++) {
            float mx = -INFINITY;
#pragma unroll
            for (int n8 = 0; n8 < 8; n8++)
                mx = fmaxf(mx, fmaxf(sc[n8][2 * r], sc[n8][2 * r + 1]));
            mx = fmaxf(mx, __shfl_xor_sync(0xffffffffu, mx, 1));
            mx = fmaxf(mx, __shfl_xor_sync(0xffffffffu, mx, 2));
            const float mnew  = fmaxf(m_i[r], mx);
            const float alpha = __expf(m_i[r] - mnew);
            float sum = 0.0f;
#pragma unroll
            for (int n8 = 0; n8 < 8; n8++) {
                const float p0 = __expf(sc[n8][2 * r]     - mnew);
                const float p1 = __expf(sc[n8][2 * r + 1] - mnew);
                sc[n8][2 * r] = p0; sc[n8][2 * r + 1] = p1;
                sum += p0 + p1;
            }
            sum += __shfl_xor_sync(0xffffffffu, sum, 1);
            sum += __shfl_xor_sync(0xffffffffu, sum, 2);
            l_i[r] = l_i[r] * alpha + sum;
            m_i[r] = mnew;
#pragma unroll
            for (int n8 = 0; n8 < 8; n8++) {
                o[n8][2 * r] *= alpha; o[n8][2 * r + 1] *= alpha;
            }
        }

        uint32_t pah[4][4], pal[4][4];
#pragma unroll
        for (int j = 0; j < 4; j++) {
#pragma unroll
            for (int u = 0; u < 4; u++) {
                const int tile = 2 * j + (u >> 1);
                const int ci   = (u & 1) * 2;
                const float p0 = sc[tile][ci], p1 = sc[tile][ci + 1];
                pah[j][u] = bf2(p0, p1);
                pal[j][u] = bf2(p0 - bf16rt(p0), p1 - bf16rt(p1));
            }
        }

#pragma unroll
        for (int j = 0; j < 4; j++) {
            const int mrow = 16 * j + ((lane >> 3) & 1) * 8 + (lane & 7);
            uint32_t vf_h[4][4], vf_l[4][4];
#pragma unroll
            for (int hp = 0; hp < 4; hp++) {
                const int chv = hp * 2 + (lane >> 4);
                ldm_x4_t(vf_h[hp], vhb + swz(mrow, chv));
                ldm_x4_t(vf_l[hp], vlb + swz(mrow, chv));
            }
#pragma unroll
            for (int n8 = 0; n8 < 8; n8++) {
                const int hp = n8 >> 1, q_ = n8 & 1;
                mma16816(o[n8], pah[j], vf_h[hp][2 * q_], vf_h[hp][2 * q_ + 1]);
                mma16816(o[n8], pal[j], vf_h[hp][2 * q_], vf_h[hp][2 * q_ + 1]);
                mma16816(o[n8], pah[j], vf_l[hp][2 * q_], vf_l[hp][2 * q_ + 1]);
            }
        }
        __syncthreads();
    }

#pragma unroll
    for (int r = 0; r < 2; r++) {
        const float inv = 1.0f / l_i[r];
        const int m = qt * 64 + wr0 + rl + r * 8;
        const size_t rowoff = ((size_t)b * Sq + m) * Dm + h * HDd;
#pragma unroll
        for (int n8 = 0; n8 < 8; n8++) {
            const int col = n8 * 8 + cbase;
            const float v0 = o[n8][2 * r] * inv;
            const float v1 = o[n8][2 * r + 1] * inv;
            ((uint32_t*)(Ch + rowoff + col))[0] = bf2(v0, v1);
            ((uint32_t*)(Cl + rowoff + col))[0] =
                bf2(v0 - bf16rt(v0), v1 - bf16rt(v1));
        }
    }
}

// ---------------------------------------------------------------------------
// Launch
// ---------------------------------------------------------------------------
extern "C" void kernel_launch(void* const* d_in, const int* in_sizes, int n_in,
                              void* d_out, int out_size)
{
    const float* x  = nullptr;
    const int*   am = nullptr;
    const float* Ws[4] = {nullptr, nullptr, nullptr, nullptr};
    const float* bs[4] = {nullptr, nullptr, nullptr, nullptr};
    int wi = 0, bi = 0;
    for (int i = 0; i < n_in; i++) {
        const long sz = in_sizes[i];
        if (sz == (long)Mtot * Dm)      x = (const float*)d_in[i];
        else if (sz == (long)Mtot)      am = (const int*)d_in[i];
        else if (sz == (long)Dm * Dm) { if (wi < 4) Ws[wi++] = (const float*)d_in[i]; }
        else if (sz == (long)Dm)      { if (bi < 4) bs[bi++] = (const float*)d_in[i]; }
    }

    __nv_bfloat16 *xh, *xl, *wh, *wl, *qh, *ql, *kh, *kl, *vh, *vl, *ch, *cl;
    cudaGetSymbolAddress((void**)&xh, g_xh);
    cudaGetSymbolAddress((void**)&xl, g_xl);
    cudaGetSymbolAddress((void**)&wh, g_wh);
    cudaGetSymbolAddress((void**)&wl, g_wl);
    cudaGetSymbolAddress((void**)&qh, g_qh);
    cudaGetSymbolAddress((void**)&ql, g_ql);
    cudaGetSymbolAddress((void**)&kh, g_kh);
    cudaGetSymbolAddress((void**)&kl, g_kl);
    cudaGetSymbolAddress((void**)&vh, g_vh);
    cudaGetSymbolAddress((void**)&vl, g_vl);
    cudaGetSymbolAddress((void**)&ch, g_ch);
    cudaGetSymbolAddress((void**)&cl, g_cl);

    cudaFuncSetAttribute(hmma_gemm_kernel<true>,
                         cudaFuncAttributeMaxDynamicSharedMemorySize, GEMM_SMEM);
    cudaFuncSetAttribute(hmma_gemm_kernel<false>,
                         cudaFuncAttributeMaxDynamicSharedMemorySize, GEMM_SMEM);
    cudaFuncSetAttribute(fa_hmma_kernel,
                         cudaFuncAttributeMaxDynamicSharedMemorySize, FA_SMEM);

    // Split inputs into bf16 hi/lo
    const int n4x = Mtot * Dm / 4;
    const int n4w = Dm * Dm / 4;
    cvt_split_kernel<<<(n4x + 255) / 256, 256>>>(x, xh, xl, n4x);
    cvt_split_w_kernel<<<dim3((n4w + 255) / 256, 4), 256>>>(
        Ws[0], Ws[1], Ws[2], Ws[3], wh, wl);

    const size_t WSZ = (size_t)Dm * Dm;

    // Fused Q/K/V projections (z selects W), Q carries softmax scale
    const dim3 gqkv(Dm / 128, Mtot / 128, 3);
    hmma_gemm_kernel<true><<<gqkv, 256, GEMM_SMEM>>>(
        xh, xl,
        wh + 0 * WSZ, wh + 1 * WSZ, wh + 2 * WSZ,
        wl + 0 * WSZ, wl + 1 * WSZ, wl + 2 * WSZ,
        bs[0], bs[1], bs[2],
        nullptr,
        qh, kh, vh,
        ql, kl, vl);

    // Attention (HMMA)
    const dim3 ga(Sq / 64, Hh, Bc);
    fa_hmma_kernel<<<ga, 128, FA_SMEM>>>(qh, ql, kh, kl, vh, vl, am, ch, cl);

    // Output projection
    const dim3 gg(Dm / 128, Mtot / 128, 1);
    hmma_gemm_kernel<false><<<gg, 256, GEMM_SMEM>>>(
        ch, cl,
        wh + 3 * WSZ, wh + 3 * WSZ, wh + 3 * WSZ,
        wl + 3 * WSZ, wl + 3 * WSZ, wl + 3 * WSZ,
        bs[3], bs[3], bs[3],
        (float*)d_out,
        nullptr, nullptr, nullptr,
        nullptr, nullptr, nullptr);
}

// round 6
// speedup vs baseline: 3.1876x; 1.0534x over previous
#include <cuda_runtime.h>
#include <cuda_bf16.h>
#include <math.h>
#include <stdint.h>

// Problem constants
constexpr int Bc  = 4;
constexpr int Sq  = 2048;
constexpr int Dm  = 1024;
constexpr int Hh  = 16;
constexpr int HDd = 64;
constexpr int Mtot = Bc * Sq;           // 8192

// Scratch (device globals: allocation-free per harness rules)
__device__ __nv_bfloat16 g_xh[(size_t)Mtot * Dm];
__device__ __nv_bfloat16 g_xl[(size_t)Mtot * Dm];
__device__ __nv_bfloat16 g_wh[(size_t)4 * Dm * Dm];
__device__ __nv_bfloat16 g_wl[(size_t)4 * Dm * Dm];
__device__ __nv_bfloat16 g_qh[(size_t)Mtot * Dm];
__device__ __nv_bfloat16 g_ql[(size_t)Mtot * Dm];
__device__ __nv_bfloat16 g_kh[(size_t)Mtot * Dm];
__device__ __nv_bfloat16 g_kl[(size_t)Mtot * Dm];
__device__ __nv_bfloat16 g_vh[(size_t)Mtot * Dm];
__device__ __nv_bfloat16 g_vl[(size_t)Mtot * Dm];
__device__ __nv_bfloat16 g_ch[(size_t)Mtot * Dm];
__device__ __nv_bfloat16 g_cl[(size_t)Mtot * Dm];

// ---------------------------------------------------------------------------
// PTX helpers (sm_80-compatible subset: ldmatrix / mma.sync / cp.async)
// ---------------------------------------------------------------------------
__device__ __forceinline__ uint32_t smem_u32(const void* p) {
    uint32_t a;
    asm("{ .reg .u64 t; cvta.to.shared.u64 t, %1; cvt.u32.u64 %0, t; }" : "=r"(a) : "l"(p));
    return a;
}
__device__ __forceinline__ void ldm_x4(uint32_t (&r)[4], uint32_t saddr) {
    asm volatile("ldmatrix.sync.aligned.m8n8.x4.shared.b16 {%0,%1,%2,%3}, [%4];"
        : "=r"(r[0]), "=r"(r[1]), "=r"(r[2]), "=r"(r[3]) : "r"(saddr));
}
__device__ __forceinline__ void ldm_x4_t(uint32_t (&r)[4], uint32_t saddr) {
    asm volatile("ldmatrix.sync.aligned.m8n8.x4.trans.shared.b16 {%0,%1,%2,%3}, [%4];"
        : "=r"(r[0]), "=r"(r[1]), "=r"(r[2]), "=r"(r[3]) : "r"(saddr));
}
__device__ __forceinline__ void mma16816(float (&c)[4], const uint32_t (&a)[4],
                                         uint32_t b0, uint32_t b1) {
    asm volatile("mma.sync.aligned.m16n8k16.row.col.f32.bf16.bf16.f32 "
        "{%0,%1,%2,%3}, {%4,%5,%6,%7}, {%8,%9}, {%0,%1,%2,%3};"
        : "+f"(c[0]), "+f"(c[1]), "+f"(c[2]), "+f"(c[3])
        : "r"(a[0]), "r"(a[1]), "r"(a[2]), "r"(a[3]), "r"(b0), "r"(b1));
}
__device__ __forceinline__ void cp16(uint32_t dst, const void* src) {
    asm volatile("cp.async.cg.shared.global [%0], [%1], 16;" :: "r"(dst), "l"(src) : "memory");
}
#define CP_COMMIT() asm volatile("cp.async.commit_group;" ::: "memory")
#define CP_WAIT(n)  asm volatile("cp.async.wait_group %0;" :: "n"(n) : "memory")

__device__ __forceinline__ uint32_t bf2(float a, float b) {
    __nv_bfloat162 t = __floats2bfloat162_rn(a, b);
    return *reinterpret_cast<uint32_t*>(&t);
}
__device__ __forceinline__ float bf16rt(float a) {
    return __bfloat162float(__float2bfloat16(a));
}
__device__ __forceinline__ uint32_t swz(int row, int chunk) {
    return (uint32_t)(row * 128 + ((chunk ^ (row & 7)) * 16));
}

// ---------------------------------------------------------------------------
// fp32 -> bf16 hi/lo split conversion (x: 1D grid; weights: y-indexed 4x)
// ---------------------------------------------------------------------------
__global__ __launch_bounds__(256) void cvt_split_kernel(const float* __restrict__ in,
                                                        __nv_bfloat16* __restrict__ hi,
                                                        __nv_bfloat16* __restrict__ lo,
                                                        int n4)
{
    const int i = blockIdx.x * blockDim.x + threadIdx.x;
    if (i >= n4) return;
    const float4 v = ((const float4*)in)[i];
    union { __nv_bfloat16 b[4]; uint2 u; } H, L;
    const float vv[4] = {v.x, v.y, v.z, v.w};
#pragma unroll
    for (int j = 0; j < 4; j++) {
        H.b[j] = __float2bfloat16(vv[j]);
        L.b[j] = __float2bfloat16(vv[j] - __bfloat162float(H.b[j]));
    }
    ((uint2*)hi)[i] = H.u;
    ((uint2*)lo)[i] = L.u;
}

__global__ __launch_bounds__(256) void cvt_split_w_kernel(
    const float* __restrict__ w0, const float* __restrict__ w1,
    const float* __restrict__ w2, const float* __restrict__ w3,
    __nv_bfloat16* __restrict__ hi, __nv_bfloat16* __restrict__ lo)
{
    const int n4 = Dm * Dm / 4;
    const int i = blockIdx.x * blockDim.x + threadIdx.x;
    if (i >= n4) return;
    const int wsel = blockIdx.y;
    const float* in = wsel == 0 ? w0 : wsel == 1 ? w1 : wsel == 2 ? w2 : w3;
    const size_t off = (size_t)wsel * n4 + i;
    const float4 v = ((const float4*)in)[i];
    union { __nv_bfloat16 b[4]; uint2 u; } H, L;
    const float vv[4] = {v.x, v.y, v.z, v.w};
#pragma unroll
    for (int j = 0; j < 4; j++) {
        H.b[j] = __float2bfloat16(vv[j]);
        L.b[j] = __float2bfloat16(vv[j] - __bfloat162float(H.b[j]));
    }
    ((uint2*)hi)[off] = H.u;
    ((uint2*)lo)[off] = L.u;
}

// ---------------------------------------------------------------------------
// HMMA bf16x3 GEMM: 128x128 CTA tile, BK=32, 8 warps (2x4), cp.async 3-stage.
// blockIdx.z selects among up to 3 (W, bias, out) sets (fused Q/K/V).
// ---------------------------------------------------------------------------
constexpr int BKg = 32;
constexpr int NKC = Dm / BKg;
constexpr int TILE_BYTES = 128 * 128;
constexpr int STAGE_BYTES = 2 * TILE_BYTES;     // 32 KB (A + B tiles)
constexpr int GEMM_SMEM = 3 * STAGE_BYTES;      // 96 KB, 3-stage ring

template <bool SPLIT>
__global__ __launch_bounds__(256) void hmma_gemm_kernel(
    const __nv_bfloat16* __restrict__ Ah, const __nv_bfloat16* __restrict__ Al,
    const __nv_bfloat16* __restrict__ Bh0, const __nv_bfloat16* __restrict__ Bh1,
    const __nv_bfloat16* __restrict__ Bh2,
    const __nv_bfloat16* __restrict__ Bl0, const __nv_bfloat16* __restrict__ Bl1,
    const __nv_bfloat16* __restrict__ Bl2,
    const float* __restrict__ bias0, const float* __restrict__ bias1,
    const float* __restrict__ bias2,
    float* __restrict__ outF,
    __nv_bfloat16* __restrict__ oh0, __nv_bfloat16* __restrict__ oh1,
    __nv_bfloat16* __restrict__ oh2,
    __nv_bfloat16* __restrict__ ol0, __nv_bfloat16* __restrict__ ol1,
    __nv_bfloat16* __restrict__ ol2)
{
    extern __shared__ char sm[];
    const uint32_t smb = smem_u32(sm);
    const int z    = blockIdx.z;
    const __nv_bfloat16* Bh = z == 0 ? Bh0 : z == 1 ? Bh1 : Bh2;
    const __nv_bfloat16* Bl = z == 0 ? Bl0 : z == 1 ? Bl1 : Bl2;
    const float* bias       = z == 0 ? bias0 : z == 1 ? bias1 : bias2;
    __nv_bfloat16* outH     = z == 0 ? oh0 : z == 1 ? oh1 : oh2;
    __nv_bfloat16* outL     = z == 0 ? ol0 : z == 1 ? ol1 : ol2;
    const float scale = (SPLIT && z == 0) ? 0.125f : 1.0f;

    const int t    = threadIdx.x;
    const int wid  = t >> 5;
    const int lane = t & 31;
    const int m0   = blockIdx.y * 128;
    const int n0   = blockIdx.x * 128;
    const int wm   = (wid & 1) * 64;
    const int wn   = (wid >> 1) * 32;

    auto load_stage = [&](int s, int kc) {
        const uint32_t ab = smb + s * STAGE_BYTES;
        const uint32_t bb = ab + TILE_BYTES;
#pragma unroll
        for (int i = 0; i < 4; i++) {
            const int idx  = t + i * 256;
            const int row  = idx >> 3;
            const int c    = idx & 7;
            const int kofs = kc * BKg + (c & 3) * 8;
            const __nv_bfloat16* sa = (c < 4 ? Ah : Al) + (size_t)(m0 + row) * Dm + kofs;
            cp16(ab + swz(row, c), sa);
            const __nv_bfloat16* sb = (c < 4 ? Bh : Bl) + (size_t)(n0 + row) * Dm + kofs;
            cp16(bb + swz(row, c), sb);
        }
        CP_COMMIT();
    };

    float acc[4][4][4];
#pragma unroll
    for (int i = 0; i < 4; i++)
#pragma unroll
        for (int j = 0; j < 4; j++)
#pragma unroll
            for (int r = 0; r < 4; r++) acc[i][j][r] = 0.0f;

    load_stage(0, 0);
    load_stage(1, 1);

    const int lrow = lane & 15;
    const int lsel = lane >> 4;

    int s = 0;
    for (int kc = 0; kc < NKC; kc++) {
        if (kc + 1 < NKC) { CP_WAIT(1); } else { CP_WAIT(0); }
        __syncthreads();
        if (kc + 2 < NKC) {
            int s2 = s + 2; if (s2 >= 3) s2 -= 3;
            load_stage(s2, kc + 2);
        }

        const uint32_t ab = smb + s * STAGE_BYTES;
        const uint32_t bb = ab + TILE_BYTES;

#pragma unroll
        for (int k16 = 0; k16 < 2; k16++) {
            const int ch = k16 * 2 + lsel;
            uint32_t a_h[4][4], a_l[4][4];
#pragma unroll
            for (int mt = 0; mt < 4; mt++) {
                const int row = wm + mt * 16 + lrow;
                ldm_x4(a_h[mt], ab + swz(row, ch));
                ldm_x4(a_l[mt], ab + swz(row, ch + 4));
            }
            uint32_t b_h[2][4], b_l[2][4];
#pragma unroll
            for (int nt = 0; nt < 2; nt++) {
                const int row = wn + nt * 16 + lrow;
                ldm_x4(b_h[nt], bb + swz(row, ch));
                ldm_x4(b_l[nt], bb + swz(row, ch + 4));
            }
#pragma unroll
            for (int mt = 0; mt < 4; mt++) {
#pragma unroll
                for (int n8 = 0; n8 < 4; n8++) {
                    const int nt = n8 >> 1, sl = n8 & 1;
                    mma16816(acc[mt][n8], a_h[mt], b_h[nt][sl], b_h[nt][sl + 2]);
                    mma16816(acc[mt][n8], a_h[mt], b_l[nt][sl], b_l[nt][sl + 2]);
                    mma16816(acc[mt][n8], a_l[mt], b_h[nt][sl], b_h[nt][sl + 2]);
                }
            }
        }
        if (++s == 3) s = 0;
    }

#pragma unroll
    for (int mt = 0; mt < 4; mt++) {
#pragma unroll
        for (int n8 = 0; n8 < 4; n8++) {
            const int r0 = m0 + wm + mt * 16 + (lane >> 2);
            const int c0 = n0 + wn + n8 * 8 + (lane & 3) * 2;
#pragma unroll
            for (int half = 0; half < 2; half++) {
                const int m = r0 + half * 8;
                const int b_ = m / Sq;
                const int s_ = m % Sq;
                const float v0 = (acc[mt][n8][half * 2 + 0] + bias[c0]) * scale;
                const float v1 = (acc[mt][n8][half * 2 + 1] + bias[c0 + 1]) * scale;
                if (SPLIT) {
                    const int h_ = c0 >> 6;
                    const int d_ = c0 & 63;
                    const size_t off =
                        ((((size_t)(b_ * Hh + h_)) * Sq + s_) * HDd + d_) >> 1;
                    ((uint32_t*)outH)[off] = bf2(v0, v1);
                    ((uint32_t*)outL)[off] = bf2(v0 - bf16rt(v0), v1 - bf16rt(v1));
                } else {
                    float* dst = outF + (size_t)m * Dm + c0;
                    dst[0] = v0; dst[1] = v1;
                }
            }
        }
    }
}

// ---------------------------------------------------------------------------
// HMMA flash attention: CTA = (64 queries, head, batch), 4 warps x 16 rows.
// SMEM: Q 16KB | K 2-stage 2x16KB | V 1-stage 16KB | mask 2x256B = 66KB
// -> 3 CTAs/SM (was 2). V load for tile i issued at top of iter i, completes
// under the S/softmax shadow; K(i+1)+mask prefetch across the whole iter.
// ---------------------------------------------------------------------------
constexpr int FA_Q    = 16384;
constexpr int FA_KST  = 16384;                 // one K stage (hi+lo)
constexpr int FA_VOFF = FA_Q + 2 * FA_KST;     // 49152
constexpr int FA_MOFF = FA_VOFF + 16384;       // 65536
constexpr int FA_SMEM = FA_MOFF + 512;         // 66048

__global__ __launch_bounds__(128, 3) void fa_hmma_kernel(
    const __nv_bfloat16* __restrict__ Qh, const __nv_bfloat16* __restrict__ Ql,
    const __nv_bfloat16* __restrict__ Kh, const __nv_bfloat16* __restrict__ Kl,
    const __nv_bfloat16* __restrict__ Vh, const __nv_bfloat16* __restrict__ Vl,
    const int* __restrict__ maskg,
    __nv_bfloat16* __restrict__ Ch, __nv_bfloat16* __restrict__ Cl)
{
    extern __shared__ char sm[];
    const uint32_t smb = smem_u32(sm);
    const int t    = threadIdx.x;
    const int w    = t >> 5;
    const int lane = t & 31;
    const int qt   = blockIdx.x;
    const int h    = blockIdx.y;
    const int b    = blockIdx.z;
    const size_t hb = ((size_t)(b * Hh + h)) * Sq * HDd;

    const uint32_t qhb = smb;
    const uint32_t qlb = smb + 8192;
    const uint32_t vhb = smb + FA_VOFF;
    const uint32_t vlb = smb + FA_VOFF + 8192;

    // K-stage loader (includes mask for that tile); one commit group.
    auto load_k = [&](int s, int kt2) {
        const uint32_t kb = smb + FA_Q + s * FA_KST;
        const char* sKH = (const char*)(Kh + hb + (size_t)kt2 * 64 * HDd);
        const char* sKL = (const char*)(Kl + hb + (size_t)kt2 * 64 * HDd);
#pragma unroll
        for (int i = 0; i < 4; i++) {
            const int idx = t + i * 128;
            const int row = idx >> 3, c = idx & 7;
            cp16(kb + swz(row, c), sKH + idx * 16);
            cp16(kb + 8192 + swz(row, c), sKL + idx * 16);
        }
        if (t < 16) cp16(smb + FA_MOFF + s * 256 + t * 16,
                         maskg + b * Sq + kt2 * 64 + t * 4);
        CP_COMMIT();
    };
    auto load_v = [&](int kt2) {
        const char* sVH = (const char*)(Vh + hb + (size_t)kt2 * 64 * HDd);
        const char* sVL = (const char*)(Vl + hb + (size_t)kt2 * 64 * HDd);
#pragma unroll
        for (int i = 0; i < 4; i++) {
            const int idx = t + i * 128;
            const int row = idx >> 3, c = idx & 7;
            cp16(vhb + swz(row, c), sVH + idx * 16);
            cp16(vlb + swz(row, c), sVL + idx * 16);
        }
        CP_COMMIT();
    };

    // Prologue: Q tile + K(0) + mask(0) in one group.
    {
        const char* srcH = (const char*)(Qh + hb + (size_t)qt * 64 * HDd);
        const char* srcL = (const char*)(Ql + hb + (size_t)qt * 64 * HDd);
#pragma unroll
        for (int i = 0; i < 4; i++) {
            const int idx = t + i * 128;
            const int row = idx >> 3, c = idx & 7;
            cp16(qhb + swz(row, c), srcH + idx * 16);
            cp16(qlb + swz(row, c), srcL + idx * 16);
        }
    }
    load_k(0, 0);

    const int lrow  = lane & 15;
    const int lsel  = lane >> 4;
    const int rl    = lane >> 2;
    const int cbase = (lane & 3) * 2;
    const int wr0   = w * 16;

    float m_i[2] = {-INFINITY, -INFINITY};
    float l_i[2] = {0.0f, 0.0f};
    float o[8][4];
#pragma unroll
    for (int n8 = 0; n8 < 8; n8++)
#pragma unroll
        for (int c = 0; c < 4; c++) o[n8][c] = 0.0f;

    for (int kt2 = 0; kt2 <= qt; kt2++) {
        const int s = kt2 & 1;

        __syncthreads();            // V buffer free (PV of prev tile done)
        load_v(kt2);                // completes under S/softmax below
        if (kt2 < qt) { load_k(s ^ 1, kt2 + 1); CP_WAIT(2); }
        else          { CP_WAIT(1); }
        __syncthreads();            // K(kt2)+mask visible to all warps

        const uint32_t khb = smb + FA_Q + s * FA_KST;
        const uint32_t klb = khb + 8192;
        const int* msk = (const int*)(sm + FA_MOFF + s * 256);

        // ---- S = Q @ K^T (bf16x3) ----
        float sc[8][4];
#pragma unroll
        for (int n8 = 0; n8 < 8; n8++)
#pragma unroll
            for (int c = 0; c < 4; c++) sc[n8][c] = 0.0f;

#pragma unroll
        for (int k16 = 0; k16 < 4; k16++) {
            const int ch = k16 * 2 + lsel;
            uint32_t qf_h[4], qf_l[4];
            ldm_x4(qf_h, qhb + swz(wr0 + lrow, ch));
            ldm_x4(qf_l, qlb + swz(wr0 + lrow, ch));
            uint32_t kf_h[4][4], kf_l[4][4];
#pragma unroll
            for (int nt = 0; nt < 4; nt++) {
                ldm_x4(kf_h[nt], khb + swz(nt * 16 + lrow, ch));
                ldm_x4(kf_l[nt], klb + swz(nt * 16 + lrow, ch));
            }
#pragma unroll
            for (int n8 = 0; n8 < 8; n8++) {
                const int nt = n8 >> 1, sl = n8 & 1;
                mma16816(sc[n8], qf_h, kf_h[nt][sl], kf_h[nt][sl + 2]);
                mma16816(sc[n8], qf_h, kf_l[nt][sl], kf_l[nt][sl + 2]);
                mma16816(sc[n8], qf_l, kf_h[nt][sl], kf_h[nt][sl + 2]);
            }
        }

        // ---- masking (pad overrides causal, reference order) ----
        const bool diag = (kt2 == qt);
        const int qi0 = qt * 64 + wr0 + rl;
#pragma unroll
        for (int n8 = 0; n8 < 8; n8++) {
#pragma unroll
            for (int c = 0; c < 4; c++) {
                const int colL = n8 * 8 + cbase + (c & 1);
                const int mv = msk[colL];
                if (mv == 0) sc[n8][c] = -1e9f;
                else if (diag) {
                    const int kj = kt2 * 64 + colL;
                    const int qi = qi0 + (c >> 1) * 8;
                    if (kj > qi) sc[n8][c] = -INFINITY;
                }
            }
        }

        // ---- online softmax (rows rl, rl+8) ----
#pragma unroll
        for (int r = 0; r < 2; r++) {
            float mx = -INFINITY;
#pragma unroll
            for (int n8 = 0; n8 < 8; n8++)
                mx = fmaxf(mx, fmaxf(sc[n8][2 * r], sc[n8][2 * r + 1]));
            mx = fmaxf(mx, __shfl_xor_sync(0xffffffffu, mx, 1));
            mx = fmaxf(mx, __shfl_xor_sync(0xffffffffu, mx, 2));
            const float mnew  = fmaxf(m_i[r], mx);
            const float alpha = __expf(m_i[r] - mnew);
            float sum = 0.0f;
#pragma unroll
            for (int n8 = 0; n8 < 8; n8++) {
                const float p0 = __expf(sc[n8][2 * r]     - mnew);
                const float p1 = __expf(sc[n8][2 * r + 1] - mnew);
                sc[n8][2 * r] = p0; sc[n8][2 * r + 1] = p1;
                sum += p0 + p1;
            }
            sum += __shfl_xor_sync(0xffffffffu, sum, 1);
            sum += __shfl_xor_sync(0xffffffffu, sum, 2);
            l_i[r] = l_i[r] * alpha + sum;
            m_i[r] = mnew;
#pragma unroll
            for (int n8 = 0; n8 < 8; n8++) {
                o[n8][2 * r] *= alpha; o[n8][2 * r + 1] *= alpha;
            }
        }

        // ---- P -> bf16 hi/lo A-fragments ----
        uint32_t pah[4][4], pal[4][4];
#pragma unroll
        for (int j = 0; j < 4; j++) {
#pragma unroll
            for (int u = 0; u < 4; u++) {
                const int tile = 2 * j + (u >> 1);
                const int ci   = (u & 1) * 2;
                const float p0 = sc[tile][ci], p1 = sc[tile][ci + 1];
                pah[j][u] = bf2(p0, p1);
                pal[j][u] = bf2(p0 - bf16rt(p0), p1 - bf16rt(p1));
            }
        }

        // ---- wait V(kt2), then O += P @ V (bf16x3) ----
        if (kt2 < qt) { CP_WAIT(1); } else { CP_WAIT(0); }
        __syncthreads();            // V visible to all warps

#pragma unroll
        for (int j = 0; j < 4; j++) {
            const int mrow = 16 * j + ((lane >> 3) & 1) * 8 + (lane & 7);
            uint32_t vf_h[4][4], vf_l[4][4];
#pragma unroll
            for (int hp = 0; hp < 4; hp++) {
                const int chv = hp * 2 + (lane >> 4);
                ldm_x4_t(vf_h[hp], vhb + swz(mrow, chv));
                ldm_x4_t(vf_l[hp], vlb + swz(mrow, chv));
            }
#pragma unroll
            for (int n8 = 0; n8 < 8; n8++) {
                const int hp = n8 >> 1, q_ = n8 & 1;
                mma16816(o[n8], pah[j], vf_h[hp][2 * q_], vf_h[hp][2 * q_ + 1]);
                mma16816(o[n8], pal[j], vf_h[hp][2 * q_], vf_h[hp][2 * q_ + 1]);
                mma16816(o[n8], pah[j], vf_l[hp][2 * q_], vf_l[hp][2 * q_ + 1]);
            }
        }
    }

    // ---- normalize + write ctx hi/lo [B,S,D] ----
#pragma unroll
    for (int r = 0; r < 2; r++) {
        const float inv = 1.0f / l_i[r];
        const int m = qt * 64 + wr0 + rl + r * 8;
        const size_t rowoff = ((size_t)b * Sq + m) * Dm + h * HDd;
#pragma unroll
        for (int n8 = 0; n8 < 8; n8++) {
            const int col = n8 * 8 + cbase;
            const float v0 = o[n8][2 * r] * inv;
            const float v1 = o[n8][2 * r + 1] * inv;
            ((uint32_t*)(Ch + rowoff + col))[0] = bf2(v0, v1);
            ((uint32_t*)(Cl + rowoff + col))[0] =
                bf2(v0 - bf16rt(v0), v1 - bf16rt(v1));
        }
    }
}

// ---------------------------------------------------------------------------
// Launch
// ---------------------------------------------------------------------------
extern "C" void kernel_launch(void* const* d_in, const int* in_sizes, int n_in,
                              void* d_out, int out_size)
{
    const float* x  = nullptr;
    const int*   am = nullptr;
    const float* Ws[4] = {nullptr, nullptr, nullptr, nullptr};
    const float* bs[4] = {nullptr, nullptr, nullptr, nullptr};
    int wi = 0, bi = 0;
    for (int i = 0; i < n_in; i++) {
        const long sz = in_sizes[i];
        if (sz == (long)Mtot * Dm)      x = (const float*)d_in[i];
        else if (sz == (long)Mtot)      am = (const int*)d_in[i];
        else if (sz == (long)Dm * Dm) { if (wi < 4) Ws[wi++] = (const float*)d_in[i]; }
        else if (sz == (long)Dm)      { if (bi < 4) bs[bi++] = (const float*)d_in[i]; }
    }

    __nv_bfloat16 *xh, *xl, *wh, *wl, *qh, *ql, *kh, *kl, *vh, *vl, *ch, *cl;
    cudaGetSymbolAddress((void**)&xh, g_xh);
    cudaGetSymbolAddress((void**)&xl, g_xl);
    cudaGetSymbolAddress((void**)&wh, g_wh);
    cudaGetSymbolAddress((void**)&wl, g_wl);
    cudaGetSymbolAddress((void**)&qh, g_qh);
    cudaGetSymbolAddress((void**)&ql, g_ql);
    cudaGetSymbolAddress((void**)&kh, g_kh);
    cudaGetSymbolAddress((void**)&kl, g_kl);
    cudaGetSymbolAddress((void**)&vh, g_vh);
    cudaGetSymbolAddress((void**)&vl, g_vl);
    cudaGetSymbolAddress((void**)&ch, g_ch);
    cudaGetSymbolAddress((void**)&cl, g_cl);

    cudaFuncSetAttribute(hmma_gemm_kernel<true>,
                         cudaFuncAttributeMaxDynamicSharedMemorySize, GEMM_SMEM);
    cudaFuncSetAttribute(hmma_gemm_kernel<false>,
                         cudaFuncAttributeMaxDynamicSharedMemorySize, GEMM_SMEM);
    cudaFuncSetAttribute(fa_hmma_kernel,
                         cudaFuncAttributeMaxDynamicSharedMemorySize, FA_SMEM);

    // Split inputs into bf16 hi/lo
    const int n4x = Mtot * Dm / 4;
    const int n4w = Dm * Dm / 4;
    cvt_split_kernel<<<(n4x + 255) / 256, 256>>>(x, xh, xl, n4x);
    cvt_split_w_kernel<<<dim3((n4w + 255) / 256, 4), 256>>>(
        Ws[0], Ws[1], Ws[2], Ws[3], wh, wl);

    const size_t WSZ = (size_t)Dm * Dm;

    // Fused Q/K/V projections (z selects W), Q carries softmax scale
    const dim3 gqkv(Dm / 128, Mtot / 128, 3);
    hmma_gemm_kernel<true><<<gqkv, 256, GEMM_SMEM>>>(
        xh, xl,
        wh + 0 * WSZ, wh + 1 * WSZ, wh + 2 * WSZ,
        wl + 0 * WSZ, wl + 1 * WSZ, wl + 2 * WSZ,
        bs[0], bs[1], bs[2],
        nullptr,
        qh, kh, vh,
        ql, kl, vl);

    // Attention (HMMA, 3 CTAs/SM)
    const dim3 ga(Sq / 64, Hh, Bc);
    fa_hmma_kernel<<<ga, 128, FA_SMEM>>>(qh, ql, kh, kl, vh, vl, am, ch, cl);

    // Output projection
    const dim3 gg(Dm / 128, Mtot / 128, 1);
    hmma_gemm_kernel<false><<<gg, 256, GEMM_SMEM>>>(
        ch, cl,
        wh + 3 * WSZ, wh + 3 * WSZ, wh + 3 * WSZ,
        wl + 3 * WSZ, wl + 3 * WSZ, wl + 3 * WSZ,
        bs[3], bs[3], bs[3],
        (float*)d_out,
        nullptr, nullptr, nullptr,
        nullptr, nullptr, nullptr);
}